// round 11
// baseline (speedup 1.0000x reference)
#include <cuda_runtime.h>

#define BB 32
#define LL 200
#define KK 200
#define CC 50
#define OUTC 250
#define EPSF 1e-6f

typedef unsigned long long u64;

// packed f32x2 FMA: d = a*b + d  (two independent fp32 FMAs per instruction)
__device__ __forceinline__ void ffma2(u64& d, u64 a, u64 b){
    asm("fma.rn.f32x2 %0, %1, %2, %0;" : "+l"(d) : "l"(a), "l"(b));
}
__device__ __forceinline__ void unpk2(u64 v, float& lo, float& hi){
    asm("mov.b64 {%0, %1}, %2;" : "=f"(lo), "=f"(hi) : "l"(v));
}

// ---------------- device scratch (static allocations are allowed) ----------
__device__ float g_inv_qn[BB*LL];
__device__ float g_inv_dn[BB*LL];
__device__ float g_inv_mqn[BB*LL*CC];   // q under maxpool_M
__device__ float g_inv_mpn[BB*LL*CC];   // d under maxpool_M
__device__ float g_inv_fpn[BB*LL*CC];   // d under full_M
__device__ float g_inv_apn[BB*LL*CC];   // d under att_M
__device__ float g_inv_xpn[BB*LL*CC];   // d under max_att_M
__device__ float g_inv_xqn[BB*LL*CC];   // q under max_att_M
__device__ float g_inv_fqn[BB*CC];      // q_last under full_M
__device__ float g_fullM2T[KK*CC];
__device__ float g_attM2T[KK*CC];
__device__ float g_xattM2T[KK*CC];
__device__ float g_mpM2T[KK*CC];
__device__ float g_mpM2[CC*KK];

// ---------------- kernel 0: squared / transposed perspective matrices ------
__global__ void k_prep(const float* __restrict__ fullM, const float* __restrict__ mpM,
                       const float* __restrict__ attM,  const float* __restrict__ xattM)
{
    int idx = blockIdx.x * 256 + threadIdx.x;
    if (idx >= CC*KK) return;
    int c = idx / KK, k = idx - c*KK;
    float fm = fullM[idx];  g_fullM2T[k*CC + c] = fm*fm;
    float am = attM[idx];   g_attM2T [k*CC + c] = am*am;
    float xm = xattM[idx];  g_xattM2T[k*CC + c] = xm*xm;
    float mm = mpM[idx];    g_mpM2T  [k*CC + c] = mm*mm;
    g_mpM2[idx] = mm*mm;
}

// ---------------- kernel 1: all per-row inverse norms ----------------------
__global__ void __launch_bounds__(512) k_norms(const float* __restrict__ q_rep,
                                               const float* __restrict__ d_rep)
{
    __shared__ float qr[KK], dr[KK];
    int row = blockIdx.x;                 // b*LL + l
    int tid = threadIdx.x;
    if (tid < KK){ qr[tid] = q_rep[(size_t)row*KK + tid];
                   dr[tid] = d_rep[(size_t)row*KK + tid]; }
    __syncthreads();

    int grp = tid >> 6, c = tid & 63;
    if (grp < 6){
        if (c < CC){
            const float* rv; const float* M2T; float* outp;
            switch (grp){
                case 0:  rv = qr; M2T = g_mpM2T;   outp = g_inv_mqn; break;
                case 1:  rv = qr; M2T = g_xattM2T; outp = g_inv_xqn; break;
                case 2:  rv = dr; M2T = g_mpM2T;   outp = g_inv_mpn; break;
                case 3:  rv = dr; M2T = g_fullM2T; outp = g_inv_fpn; break;
                case 4:  rv = dr; M2T = g_attM2T;  outp = g_inv_apn; break;
                default: rv = dr; M2T = g_xattM2T; outp = g_inv_xpn; break;
            }
            float s = 0.f;
            #pragma unroll 4
            for (int k = 0; k < KK; k++){ float v = rv[k]; s += v*v*M2T[k*CC + c]; }
            outp[(size_t)row*CC + c] = 1.0f / sqrtf(fmaxf(s, EPSF));
        }
    } else if (grp == 6){
        int lane = tid & 31;
        float s = 0.f;
        for (int k = lane; k < KK; k += 32){ float v = qr[k]; s += v*v; }
        #pragma unroll
        for (int off = 16; off; off >>= 1) s += __shfl_xor_sync(0xffffffffu, s, off);
        if (lane == 0) g_inv_qn[row] = 1.0f / sqrtf(fmaxf(s, EPSF));
    } else {
        int lane = tid & 31;
        float s = 0.f;
        for (int k = lane; k < KK; k += 32){ float v = dr[k]; s += v*v; }
        #pragma unroll
        for (int off = 16; off; off >>= 1) s += __shfl_xor_sync(0xffffffffu, s, off);
        if (lane == 0) g_inv_dn[row] = 1.0f / sqrtf(fmaxf(s, EPSF));
    }
}

// ---------------- kernel 2: q_last norms under full_M ----------------------
__global__ void k_fqn(const float* __restrict__ q_last)
{
    __shared__ float ql[KK];
    int b = blockIdx.x;
    for (int k = threadIdx.x; k < KK; k += 64) ql[k] = q_last[(size_t)b*KK + k];
    __syncthreads();
    int c = threadIdx.x;
    if (c >= CC) return;
    float s = 0.f;
    for (int k = 0; k < KK; k++){ float v = ql[k]; s += v*v*g_fullM2T[k*CC + c]; }
    g_inv_fqn[b*CC + c] = 1.0f / sqrtf(fmaxf(s, EPSF));
}

// ---------------- kernel 3: rel / wq / full / att / max-att (GEMM-style) ---
#define RT 25                              // rows per tile
#define RKC 40                             // k-chunk for q transpose staging
#define DS_STR 204
#define REL_STR 208
#define WQ_STR 204
#define QS_STR 209
#define OFF_DSM   0
#define OFF_REL   (OFF_DSM + RT*DS_STR)
#define OFF_WQ    (OFF_REL + RT*REL_STR)
#define OFF_QSM   (OFF_WQ  + RT*WQ_STR)
#define OFF_QSC   (OFF_QSM + RKC*QS_STR)
#define OFF_QL    (OFF_QSC + 200)
#define OFF_ISC   (OFF_QL  + 200)
#define OFF_IRS   (OFF_ISC + 32)
#define OFF_BJ    (OFF_IRS + 32)
#define RM_FLOATS (OFF_BJ + 32)
#define RM_SMEM   (RM_FLOATS*4)

__global__ void __launch_bounds__(256) k_relmatch2(
    const float* __restrict__ q_rep, const float* __restrict__ q_last,
    const float* __restrict__ q_mask, const float* __restrict__ d_rep,
    const float* __restrict__ d_mask, float* __restrict__ out)
{
    extern __shared__ float sm[];
    float* dsm    = sm + OFF_DSM;
    float* relsm  = sm + OFF_REL;
    float* wqsm   = sm + OFF_WQ;
    float* qsm    = sm + OFF_QSM;
    float* qscale = sm + OFF_QSC;
    float* qlsm   = sm + OFF_QL;
    float* iscale = sm + OFF_ISC;
    float* irs    = sm + OFF_IRS;
    int*   bjsm   = (int*)(sm + OFF_BJ);

    int b  = blockIdx.x >> 3;
    int it = blockIdx.x & 7;
    int i0g = it * RT;
    int tid = threadIdx.x;
    const float* qb = q_rep + (size_t)b*LL*KK;
    const float* db = d_rep + (size_t)b*LL*KK + (size_t)i0g*KK;

    for (int idx = tid; idx < RT*KK; idx += 256){
        int i = idx / KK, k = idx - i*KK;
        dsm[i*DS_STR + k] = db[idx];
    }
    for (int j = tid; j < LL; j += 256)
        qscale[j] = g_inv_qn[b*LL + j] * q_mask[b*LL + j];
    for (int k = tid; k < KK; k += 256)
        qlsm[k] = q_last[(size_t)b*KK + k];
    if (tid < RT){
        int row = b*LL + i0g + tid;
        iscale[tid] = g_inv_dn[row] * d_mask[row];
    }
    __syncthreads();

    // ---- phase 1: rel GEMM ----
    int ig = tid / 40, jg = tid % 40;
    float acc[5][5];
    #pragma unroll
    for (int r = 0; r < 5; r++)
        #pragma unroll
        for (int jj = 0; jj < 5; jj++) acc[r][jj] = 0.f;

    for (int k0 = 0; k0 < KK; k0 += RKC){
        for (int idx = tid; idx < RKC*LL; idx += 256){
            int j = idx / RKC, kk = idx - j*RKC;
            qsm[kk*QS_STR + j] = qb[(size_t)j*KK + k0 + kk];
        }
        __syncthreads();
        if (tid < 200){
            #pragma unroll 4
            for (int kk = 0; kk < RKC; kk++){
                float a[5], qv[5];
                #pragma unroll
                for (int r = 0; r < 5; r++)  a[r]  = dsm[(ig*5+r)*DS_STR + k0 + kk];
                #pragma unroll
                for (int jj = 0; jj < 5; jj++) qv[jj] = qsm[kk*QS_STR + jg*5 + jj];
                #pragma unroll
                for (int r = 0; r < 5; r++)
                    #pragma unroll
                    for (int jj = 0; jj < 5; jj++) acc[r][jj] += a[r]*qv[jj];
            }
        }
        __syncthreads();
    }
    if (tid < 200){
        #pragma unroll
        for (int r = 0; r < 5; r++){
            int i = ig*5 + r; float isc = iscale[i];
            #pragma unroll
            for (int jj = 0; jj < 5; jj++){
                int j = jg*5 + jj;
                relsm[i*REL_STR + j] = acc[r][jj] * qscale[j] * isc;
            }
        }
    }
    __syncthreads();

    // ---- phase 2: per-row sum + first-occurrence argmax ----
    {
        int w = tid >> 5, lane = tid & 31;
        for (int i = w; i < RT; i += 8){
            float s = 0.f, bv = -3.402823466e38f; int bi = 0;
            for (int j = lane; j < LL; j += 32){
                float v = relsm[i*REL_STR + j];
                s += v;
                if (v > bv){ bv = v; bi = j; }
            }
            #pragma unroll
            for (int off = 16; off; off >>= 1){
                s += __shfl_xor_sync(0xffffffffu, s, off);
                float ov = __shfl_xor_sync(0xffffffffu, bv, off);
                int   oi = __shfl_xor_sync(0xffffffffu, bi, off);
                if (ov > bv || (ov == bv && oi < bi)){ bv = ov; bi = oi; }
            }
            if (lane == 0){ irs[i] = 1.0f / (s + EPSF); bjsm[i] = bi; }
        }
    }
    __syncthreads();

    // ---- phase 3: wq GEMM ----
    if (tid < 250){
        int ig2 = tid / 50, kg = tid % 50;
        float a0[5], a1[5], a2[5], a3[5];
        #pragma unroll
        for (int r = 0; r < 5; r++){ a0[r]=0.f; a1[r]=0.f; a2[r]=0.f; a3[r]=0.f; }
        const float4* qb4 = (const float4*)qb;
        for (int j = 0; j < LL; j++){
            float4 qv = qb4[j*50 + kg];
            #pragma unroll
            for (int r = 0; r < 5; r++){
                float rv = relsm[(ig2*5+r)*REL_STR + j];
                a0[r] += rv*qv.x; a1[r] += rv*qv.y;
                a2[r] += rv*qv.z; a3[r] += rv*qv.w;
            }
        }
        #pragma unroll
        for (int r = 0; r < 5; r++){
            int i = ig2*5 + r; float inv = irs[i];
            float* wp = wqsm + i*WQ_STR + kg*4;
            wp[0] = a0[r]*inv; wp[1] = a1[r]*inv; wp[2] = a2[r]*inv; wp[3] = a3[r]*inv;
        }
    }
    __syncthreads();

    // ---- phase 4: output columns (full / att / max-att) ----
    for (int idx = tid; idx < RT*150; idx += 256){
        int i = idx / 150, o = idx - i*150;
        int grp = o / 50, c = o - grp*50;
        int row = b*LL + i0g + i;
        const float* drow = dsm + i*DS_STR;
        if (grp == 0){
            float s = 0.f;
            #pragma unroll 4
            for (int k = 0; k < KK; k++) s += drow[k]*qlsm[k]*g_fullM2T[k*CC + c];
            out[(size_t)row*OUTC + c] = s * g_inv_fpn[(size_t)row*CC + c]
                                          * g_inv_fqn[b*CC + c];
        } else if (grp == 1){
            const float* wrow = wqsm + i*WQ_STR;
            float sn = 0.f, sq = 0.f;
            #pragma unroll 4
            for (int k = 0; k < KK; k++){
                float m2 = g_attM2T[k*CC + c];
                float wv = wrow[k];
                sn += drow[k]*wv*m2;
                sq += wv*wv*m2;
            }
            out[(size_t)row*OUTC + 150 + c] =
                sn * g_inv_apn[(size_t)row*CC + c] * (1.0f / sqrtf(fmaxf(sq, EPSF)));
        } else {
            int bj = bjsm[i];
            const float* qrow = qb + (size_t)bj*KK;
            float s = 0.f;
            #pragma unroll 4
            for (int k = 0; k < KK; k++) s += drow[k]*qrow[k]*g_xattM2T[k*CC + c];
            out[(size_t)row*OUTC + 200 + c] = s * g_inv_xpn[(size_t)row*CC + c]
                                                * g_inv_xqn[(size_t)(b*LL + bj)*CC + c];
        }
    }
}

// ---------------- kernel 4: maxpool matching — FFMA2 (f32x2) hot loop ------
// block = (b, c). A[i][k] = d*M2[c]*inv_mpn in smem (XOR-swizzled float4),
// q chunks pre-scaled by inv_mqn. Thread tile 8i x 5j; inner loop packs the
// 4 k-values of each float4 into two f32x2 pairs -> 80 FFMA2 per k4 instead
// of 160 FFMA. One packed accumulator per (r,jj); halves summed in epilogue.
#define JC 40
#define TJ 5
#define ASTRIDE 208
#define QSTRIDE 204
#define A_FLOATS (LL*ASTRIDE)
#define Q_FLOATS (JC*QSTRIDE)
#define MP_SMEM ((A_FLOATS + Q_FLOATS)*4)

__global__ void __launch_bounds__(224, 1) k_maxpool(const float* __restrict__ q_rep,
                                                    const float* __restrict__ d_rep,
                                                    float* __restrict__ out)
{
    extern __shared__ float sm[];
    float* Asm = sm;
    float* qsm = sm + A_FLOATS;
    int b = blockIdx.x / CC;
    int c = blockIdx.x - b*CC;
    int tid = threadIdx.x;

    const float* drow = d_rep + (size_t)b*LL*KK;
    const float* m2   = g_mpM2 + (size_t)c*KK;
    for (int idx = tid; idx < LL*KK; idx += 224){
        int i = idx / KK, k = idx - i*KK;
        int phys = i*ASTRIDE + ((((k >> 2) ^ ((i >> 3) & 3)) << 2) | (k & 3));
        Asm[phys] = drow[idx] * m2[k] * g_inv_mpn[(size_t)(b*LL + i)*CC + c];
    }

    int ig = tid >> 3;                    // 0..27 (25 active)
    int jg = tid & 7;
    int igx = ig & 3;
    bool act = (ig < 25);
    unsigned mask = __ballot_sync(0xffffffffu, act);

    float rmax[8], rsum[8];
    #pragma unroll
    for (int r = 0; r < 8; r++){ rmax[r] = -3.402823466e38f; rsum[r] = 0.f; }

    const ulonglong2* Asm2 = (const ulonglong2*)Asm;   // 16B = two f32x2 pairs
    const ulonglong2* qsm2 = (const ulonglong2*)qsm;
    int abase = ig*8*52;                  // 16B-slot index of first owned A row
    int qbase = jg*TJ*51;                 // 16B-slot index of first owned q row

    for (int j0 = 0; j0 < LL; j0 += JC){
        __syncthreads();
        for (int idx = tid; idx < JC*KK; idx += 224){
            int j = idx / KK, k = idx - j*KK;
            qsm[j*QSTRIDE + k] = q_rep[((size_t)b*LL + j0 + j)*KK + k]
                               * g_inv_mqn[(size_t)(b*LL + j0 + j)*CC + c];
        }
        __syncthreads();

        if (act){
            u64 acc[8][TJ];               // packed: two fp32 partial sums each
            #pragma unroll
            for (int r = 0; r < 8; r++)
                #pragma unroll
                for (int jj = 0; jj < TJ; jj++) acc[r][jj] = 0ULL;

            #pragma unroll 2
            for (int k4 = 0; k4 < KK/4; k4++){
                ulonglong2 qv[TJ];
                #pragma unroll
                for (int jj = 0; jj < TJ; jj++) qv[jj] = qsm2[qbase + jj*51 + k4];
                int ak = k4 ^ igx;
                #pragma unroll
                for (int r = 0; r < 8; r++){
                    ulonglong2 av = Asm2[abase + r*52 + ak];
                    #pragma unroll
                    for (int jj = 0; jj < TJ; jj++){
                        ffma2(acc[r][jj], av.x, qv[jj].x);
                        ffma2(acc[r][jj], av.y, qv[jj].y);
                    }
                }
            }
            #pragma unroll
            for (int r = 0; r < 8; r++){
                float lmax, lsum;
                {
                    float lo, hi; unpk2(acc[r][0], lo, hi);
                    float v = lo + hi; lmax = v; lsum = v;
                }
                #pragma unroll
                for (int jj = 1; jj < TJ; jj++){
                    float lo, hi; unpk2(acc[r][jj], lo, hi);
                    float v = lo + hi;
                    lmax = fmaxf(lmax, v);
                    lsum += v;
                }
                #pragma unroll
                for (int off = 1; off < 8; off <<= 1){
                    lmax = fmaxf(lmax, __shfl_xor_sync(mask, lmax, off));
                    lsum += __shfl_xor_sync(mask, lsum, off);
                }
                rmax[r] = fmaxf(rmax[r], lmax);
                rsum[r] += lsum;
            }
        }
    }

    if (act && jg == 0){
        #pragma unroll
        for (int r = 0; r < 8; r++){
            int i = ig*8 + r;
            float* o = out + ((size_t)b*LL + i)*OUTC;
            o[ 50 + c] = rmax[r];
            o[100 + c] = rsum[r] * (1.0f/200.0f);
        }
    }
}

// ---------------- launcher -------------------------------------------------
extern "C" void kernel_launch(void* const* d_in, const int* in_sizes, int n_in,
                              void* d_out, int out_size)
{
    const float* q_rep  = (const float*)d_in[0];
    const float* q_last = (const float*)d_in[1];
    const float* q_mask = (const float*)d_in[2];
    const float* d_rep  = (const float*)d_in[3];
    // d_in[4] = d_last (unused by reference)
    const float* d_mask = (const float*)d_in[5];
    const float* fullM  = (const float*)d_in[6];
    const float* mpM    = (const float*)d_in[7];
    const float* attM   = (const float*)d_in[8];
    const float* xattM  = (const float*)d_in[9];
    float* out = (float*)d_out;

    k_prep<<<(CC*KK + 255)/256, 256>>>(fullM, mpM, attM, xattM);
    k_norms<<<BB*LL, 512>>>(q_rep, d_rep);
    k_fqn<<<BB, 64>>>(q_last);

    cudaFuncSetAttribute(k_relmatch2, cudaFuncAttributeMaxDynamicSharedMemorySize, RM_SMEM);
    k_relmatch2<<<BB*8, 256, RM_SMEM>>>(q_rep, q_last, q_mask, d_rep, d_mask, out);

    cudaFuncSetAttribute(k_maxpool, cudaFuncAttributeMaxDynamicSharedMemorySize, MP_SMEM);
    k_maxpool<<<BB*CC, 224, MP_SMEM>>>(q_rep, d_rep, out);
}

// round 13
// speedup vs baseline: 1.2796x; 1.2796x over previous
#include <cuda_runtime.h>
#include <cuda_bf16.h>
#include <cstdint>

#define BB 32
#define LL 200
#define KK 200
#define CC 50
#define OUTC 250
#define EPSF 1e-6f

// ---------------- device scratch (static allocations are allowed) ----------
__device__ float g_inv_qn[BB*LL];
__device__ float g_inv_dn[BB*LL];
__device__ float g_inv_mqn[BB*LL*CC];   // q under maxpool_M
__device__ float g_inv_mqnT[BB*CC*LL];  // transposed: [(b,c), j]
__device__ float g_inv_mpn[BB*LL*CC];   // d under maxpool_M
__device__ float g_inv_fpn[BB*LL*CC];   // d under full_M
__device__ float g_inv_apn[BB*LL*CC];   // d under att_M
__device__ float g_inv_xpn[BB*LL*CC];   // d under max_att_M
__device__ float g_inv_xqn[BB*LL*CC];   // q under max_att_M
__device__ float g_inv_fqn[BB*CC];      // q_last under full_M
__device__ float g_fullM2T[KK*CC];
__device__ float g_attM2T[KK*CC];
__device__ float g_xattM2T[KK*CC];
__device__ float g_mpM2T[KK*CC];
__device__ float g_mpM2[CC*KK];
// bf16 split of q_rep (hi + lo), built once, reused across all 50 channels
__device__ __nv_bfloat16 g_qh[BB*LL*KK];
__device__ __nv_bfloat16 g_ql[BB*LL*KK];
// maxpool partials: [jhalf][b*10240 + c*200 + i]
__device__ float g_pmax[2][BB*10240];
__device__ float g_psum[2][BB*10240];

// ---------------- warp-level bf16 MMA (generic PTX, sm_80+) ----------------
__device__ __forceinline__ void mma16816(float* d, const uint32_t* a,
                                         uint32_t b0, uint32_t b1){
    asm volatile(
        "mma.sync.aligned.m16n8k16.row.col.f32.bf16.bf16.f32 "
        "{%0,%1,%2,%3}, {%4,%5,%6,%7}, {%8,%9}, {%0,%1,%2,%3};"
        : "+f"(d[0]), "+f"(d[1]), "+f"(d[2]), "+f"(d[3])
        : "r"(a[0]), "r"(a[1]), "r"(a[2]), "r"(a[3]), "r"(b0), "r"(b1));
}

// ---------------- kernel 0: squared / transposed perspective matrices ------
__global__ void k_prep(const float* __restrict__ fullM, const float* __restrict__ mpM,
                       const float* __restrict__ attM,  const float* __restrict__ xattM)
{
    int idx = blockIdx.x * 256 + threadIdx.x;
    if (idx >= CC*KK) return;
    int c = idx / KK, k = idx - c*KK;
    float fm = fullM[idx];  g_fullM2T[k*CC + c] = fm*fm;
    float am = attM[idx];   g_attM2T [k*CC + c] = am*am;
    float xm = xattM[idx];  g_xattM2T[k*CC + c] = xm*xm;
    float mm = mpM[idx];    g_mpM2T  [k*CC + c] = mm*mm;
    g_mpM2[idx] = mm*mm;
}

// ---------------- kernel 0b: bf16 split of q_rep ---------------------------
__global__ void k_qsplit(const float* __restrict__ q_rep)
{
    int idx = blockIdx.x * 256 + threadIdx.x;
    if (idx >= BB*LL*KK) return;
    float v = q_rep[idx];
    __nv_bfloat16 h = __float2bfloat16(v);
    g_qh[idx] = h;
    g_ql[idx] = __float2bfloat16(v - __bfloat162float(h));
}

// ---------------- kernel 1: all per-row inverse norms ----------------------
__global__ void __launch_bounds__(512) k_norms(const float* __restrict__ q_rep,
                                               const float* __restrict__ d_rep)
{
    __shared__ float qr[KK], dr[KK];
    int row = blockIdx.x;                 // b*LL + l
    int tid = threadIdx.x;
    if (tid < KK){ qr[tid] = q_rep[(size_t)row*KK + tid];
                   dr[tid] = d_rep[(size_t)row*KK + tid]; }
    __syncthreads();

    int grp = tid >> 6, c = tid & 63;
    if (grp < 6){
        if (c < CC){
            const float* rv; const float* M2T; float* outp;
            switch (grp){
                case 0:  rv = qr; M2T = g_mpM2T;   outp = g_inv_mqn; break;
                case 1:  rv = qr; M2T = g_xattM2T; outp = g_inv_xqn; break;
                case 2:  rv = dr; M2T = g_mpM2T;   outp = g_inv_mpn; break;
                case 3:  rv = dr; M2T = g_fullM2T; outp = g_inv_fpn; break;
                case 4:  rv = dr; M2T = g_attM2T;  outp = g_inv_apn; break;
                default: rv = dr; M2T = g_xattM2T; outp = g_inv_xpn; break;
            }
            float s = 0.f;
            #pragma unroll 4
            for (int k = 0; k < KK; k++){ float v = rv[k]; s += v*v*M2T[k*CC + c]; }
            float inv = 1.0f / sqrtf(fmaxf(s, EPSF));
            outp[(size_t)row*CC + c] = inv;
            if (grp == 0){
                int b = row / LL, l = row - b*LL;
                g_inv_mqnT[((size_t)b*CC + c)*LL + l] = inv;
            }
        }
    } else if (grp == 6){
        int lane = tid & 31;
        float s = 0.f;
        for (int k = lane; k < KK; k += 32){ float v = qr[k]; s += v*v; }
        #pragma unroll
        for (int off = 16; off; off >>= 1) s += __shfl_xor_sync(0xffffffffu, s, off);
        if (lane == 0) g_inv_qn[row] = 1.0f / sqrtf(fmaxf(s, EPSF));
    } else {
        int lane = tid & 31;
        float s = 0.f;
        for (int k = lane; k < KK; k += 32){ float v = dr[k]; s += v*v; }
        #pragma unroll
        for (int off = 16; off; off >>= 1) s += __shfl_xor_sync(0xffffffffu, s, off);
        if (lane == 0) g_inv_dn[row] = 1.0f / sqrtf(fmaxf(s, EPSF));
    }
}

// ---------------- kernel 2: q_last norms under full_M ----------------------
__global__ void k_fqn(const float* __restrict__ q_last)
{
    __shared__ float ql[KK];
    int b = blockIdx.x;
    for (int k = threadIdx.x; k < KK; k += 64) ql[k] = q_last[(size_t)b*KK + k];
    __syncthreads();
    int c = threadIdx.x;
    if (c >= CC) return;
    float s = 0.f;
    for (int k = 0; k < KK; k++){ float v = ql[k]; s += v*v*g_fullM2T[k*CC + c]; }
    g_inv_fqn[b*CC + c] = 1.0f / sqrtf(fmaxf(s, EPSF));
}

// ---------------- kernel 3: rel / wq / full / att / max-att (unchanged) ----
#define RT 25
#define RKC 40
#define DS_STR 204
#define REL_STR 208
#define WQ_STR 204
#define QS_STR 209
#define OFF_DSM   0
#define OFF_REL   (OFF_DSM + RT*DS_STR)
#define OFF_WQ    (OFF_REL + RT*REL_STR)
#define OFF_QSM   (OFF_WQ  + RT*WQ_STR)
#define OFF_QSC   (OFF_QSM + RKC*QS_STR)
#define OFF_QL    (OFF_QSC + 200)
#define OFF_ISC   (OFF_QL  + 200)
#define OFF_IRS   (OFF_ISC + 32)
#define OFF_BJ    (OFF_IRS + 32)
#define RM_FLOATS (OFF_BJ + 32)
#define RM_SMEM   (RM_FLOATS*4)

__global__ void __launch_bounds__(256) k_relmatch2(
    const float* __restrict__ q_rep, const float* __restrict__ q_last,
    const float* __restrict__ q_mask, const float* __restrict__ d_rep,
    const float* __restrict__ d_mask, float* __restrict__ out)
{
    extern __shared__ float sm[];
    float* dsm    = sm + OFF_DSM;
    float* relsm  = sm + OFF_REL;
    float* wqsm   = sm + OFF_WQ;
    float* qsm    = sm + OFF_QSM;
    float* qscale = sm + OFF_QSC;
    float* qlsm   = sm + OFF_QL;
    float* iscale = sm + OFF_ISC;
    float* irs    = sm + OFF_IRS;
    int*   bjsm   = (int*)(sm + OFF_BJ);

    int b  = blockIdx.x >> 3;
    int it = blockIdx.x & 7;
    int i0g = it * RT;
    int tid = threadIdx.x;
    const float* qb = q_rep + (size_t)b*LL*KK;
    const float* db = d_rep + (size_t)b*LL*KK + (size_t)i0g*KK;

    for (int idx = tid; idx < RT*KK; idx += 256){
        int i = idx / KK, k = idx - i*KK;
        dsm[i*DS_STR + k] = db[idx];
    }
    for (int j = tid; j < LL; j += 256)
        qscale[j] = g_inv_qn[b*LL + j] * q_mask[b*LL + j];
    for (int k = tid; k < KK; k += 256)
        qlsm[k] = q_last[(size_t)b*KK + k];
    if (tid < RT){
        int row = b*LL + i0g + tid;
        iscale[tid] = g_inv_dn[row] * d_mask[row];
    }
    __syncthreads();

    int ig = tid / 40, jg = tid % 40;
    float acc[5][5];
    #pragma unroll
    for (int r = 0; r < 5; r++)
        #pragma unroll
        for (int jj = 0; jj < 5; jj++) acc[r][jj] = 0.f;

    for (int k0 = 0; k0 < KK; k0 += RKC){
        for (int idx = tid; idx < RKC*LL; idx += 256){
            int j = idx / RKC, kk = idx - j*RKC;
            qsm[kk*QS_STR + j] = qb[(size_t)j*KK + k0 + kk];
        }
        __syncthreads();
        if (tid < 200){
            #pragma unroll 4
            for (int kk = 0; kk < RKC; kk++){
                float a[5], qv[5];
                #pragma unroll
                for (int r = 0; r < 5; r++)  a[r]  = dsm[(ig*5+r)*DS_STR + k0 + kk];
                #pragma unroll
                for (int jj = 0; jj < 5; jj++) qv[jj] = qsm[kk*QS_STR + jg*5 + jj];
                #pragma unroll
                for (int r = 0; r < 5; r++)
                    #pragma unroll
                    for (int jj = 0; jj < 5; jj++) acc[r][jj] += a[r]*qv[jj];
            }
        }
        __syncthreads();
    }
    if (tid < 200){
        #pragma unroll
        for (int r = 0; r < 5; r++){
            int i = ig*5 + r; float isc = iscale[i];
            #pragma unroll
            for (int jj = 0; jj < 5; jj++){
                int j = jg*5 + jj;
                relsm[i*REL_STR + j] = acc[r][jj] * qscale[j] * isc;
            }
        }
    }
    __syncthreads();

    {
        int w = tid >> 5, lane = tid & 31;
        for (int i = w; i < RT; i += 8){
            float s = 0.f, bv = -3.402823466e38f; int bi = 0;
            for (int j = lane; j < LL; j += 32){
                float v = relsm[i*REL_STR + j];
                s += v;
                if (v > bv){ bv = v; bi = j; }
            }
            #pragma unroll
            for (int off = 16; off; off >>= 1){
                s += __shfl_xor_sync(0xffffffffu, s, off);
                float ov = __shfl_xor_sync(0xffffffffu, bv, off);
                int   oi = __shfl_xor_sync(0xffffffffu, bi, off);
                if (ov > bv || (ov == bv && oi < bi)){ bv = ov; bi = oi; }
            }
            if (lane == 0){ irs[i] = 1.0f / (s + EPSF); bjsm[i] = bi; }
        }
    }
    __syncthreads();

    if (tid < 250){
        int ig2 = tid / 50, kg = tid % 50;
        float a0[5], a1[5], a2[5], a3[5];
        #pragma unroll
        for (int r = 0; r < 5; r++){ a0[r]=0.f; a1[r]=0.f; a2[r]=0.f; a3[r]=0.f; }
        const float4* qb4 = (const float4*)qb;
        for (int j = 0; j < LL; j++){
            float4 qv = qb4[j*50 + kg];
            #pragma unroll
            for (int r = 0; r < 5; r++){
                float rv = relsm[(ig2*5+r)*REL_STR + j];
                a0[r] += rv*qv.x; a1[r] += rv*qv.y;
                a2[r] += rv*qv.z; a3[r] += rv*qv.w;
            }
        }
        #pragma unroll
        for (int r = 0; r < 5; r++){
            int i = ig2*5 + r; float inv = irs[i];
            float* wp = wqsm + i*WQ_STR + kg*4;
            wp[0] = a0[r]*inv; wp[1] = a1[r]*inv; wp[2] = a2[r]*inv; wp[3] = a3[r]*inv;
        }
    }
    __syncthreads();

    for (int idx = tid; idx < RT*150; idx += 256){
        int i = idx / 150, o = idx - i*150;
        int grp = o / 50, c = o - grp*50;
        int row = b*LL + i0g + i;
        const float* drow = dsm + i*DS_STR;
        if (grp == 0){
            float s = 0.f;
            #pragma unroll 4
            for (int k = 0; k < KK; k++) s += drow[k]*qlsm[k]*g_fullM2T[k*CC + c];
            out[(size_t)row*OUTC + c] = s * g_inv_fpn[(size_t)row*CC + c]
                                          * g_inv_fqn[b*CC + c];
        } else if (grp == 1){
            const float* wrow = wqsm + i*WQ_STR;
            float sn = 0.f, sq = 0.f;
            #pragma unroll 4
            for (int k = 0; k < KK; k++){
                float m2 = g_attM2T[k*CC + c];
                float wv = wrow[k];
                sn += drow[k]*wv*m2;
                sq += wv*wv*m2;
            }
            out[(size_t)row*OUTC + 150 + c] =
                sn * g_inv_apn[(size_t)row*CC + c] * (1.0f / sqrtf(fmaxf(sq, EPSF)));
        } else {
            int bj = bjsm[i];
            const float* qrow = qb + (size_t)bj*KK;
            float s = 0.f;
            #pragma unroll 4
            for (int k = 0; k < KK; k++) s += drow[k]*qrow[k]*g_xattM2T[k*CC + c];
            out[(size_t)row*OUTC + 200 + c] = s * g_inv_xpn[(size_t)row*CC + c]
                                                * g_inv_xqn[(size_t)(b*LL + bj)*CC + c];
        }
    }
}

// ---------------- kernel 4: maxpool matching via warp MMA (bf16 split) -----
// block = (b, c, jh). S[i,j] = sum_k (d_ik*M2_ck)*q_jk via
// mma.sync.m16n8k16 bf16, 3 passes: Ah*Bh + Ah*Bl + Al*Bh (fp32 accum).
// Norm scales folded into epilogue / combine (both positive).
// M = 208 (13 m16 tiles, rows >=200 zero), N = 104 (13 n8 tiles, j >=100
// masked), K chunked 4x64 (k >= 200 zero).
#define MSTR 72                            // bf16 per smem row (144 B)
#define SM_AH 0
#define SM_AL (208*MSTR)                   // 14976
#define SM_BH (2*208*MSTR)                 // 29952
#define SM_BL (SM_BH + 104*MSTR)           // 37440
#define SM_BF16 (SM_BL + 104*MSTR)         // 44928 bf16 = 89856 B
#define MM_SMEM (SM_BF16*2 + 104*4)        // + mqs[104] floats = 90272 B

__global__ void __launch_bounds__(256, 1) k_mp_mma(const float* __restrict__ d_rep)
{
    extern __shared__ __nv_bfloat16 smb[];
    __nv_bfloat16* Ah = smb + SM_AH;
    __nv_bfloat16* Al = smb + SM_AL;
    __nv_bfloat16* Bh = smb + SM_BH;
    __nv_bfloat16* Bl = smb + SM_BL;
    float* mqs = (float*)(smb + SM_BF16);

    int bx = blockIdx.x;
    int jh = bx & 1;
    int c  = (bx >> 1) % CC;
    int b  = bx / (2*CC);
    int tid = threadIdx.x, wid = tid >> 5, lane = tid & 31;
    int gid = lane >> 2, tig = lane & 3;       // row group / thread-in-group

    const float* db = d_rep + (size_t)b*LL*KK;
    const float* m2 = g_mpM2 + (size_t)c*KK;

    for (int n = tid; n < 104; n += 256)
        mqs[n] = (n < 100) ? g_inv_mqnT[((size_t)b*CC + c)*LL + jh*100 + n] : 0.f;

    float acc[2][13][4];
    #pragma unroll
    for (int s = 0; s < 2; s++)
        #pragma unroll
        for (int nt = 0; nt < 13; nt++)
            #pragma unroll
            for (int r = 0; r < 4; r++) acc[s][nt][r] = 0.f;

    int mt0 = wid, mt1 = wid + 8;
    bool m1v = (mt1 < 13);

    for (int kc = 0; kc < 4; kc++){
        int k0 = kc*64;
        __syncthreads();
        // fill A (d * M2, bf16 split)
        for (int idx = tid; idx < 208*64; idx += 256){
            int r = idx >> 6, kk = idx & 63, gk = k0 + kk;
            float v = 0.f;
            if (r < 200 && gk < 200) v = db[(size_t)r*KK + gk] * m2[gk];
            __nv_bfloat16 h = __float2bfloat16(v);
            Ah[r*MSTR + kk] = h;
            Al[r*MSTR + kk] = __float2bfloat16(v - __bfloat162float(h));
        }
        // fill B from prebuilt q split
        for (int idx = tid; idx < 104*64; idx += 256){
            int n = idx >> 6, kk = idx & 63, gk = k0 + kk;
            __nv_bfloat16 h = __float2bfloat16(0.f), l = h;
            if (n < 100 && gk < 200){
                size_t o = ((size_t)b*LL + jh*100 + n)*KK + gk;
                h = g_qh[o]; l = g_ql[o];
            }
            Bh[n*MSTR + kk] = h; Bl[n*MSTR + kk] = l;
        }
        __syncthreads();

        #pragma unroll
        for (int ks = 0; ks < 4; ks++){
            int kb = ks*16;
            uint32_t ah0[4], al0[4], ah1[4], al1[4];
            {
                const __nv_bfloat16* p = Ah + (mt0*16 + gid)*MSTR + kb + 2*tig;
                const __nv_bfloat16* q = Al + (mt0*16 + gid)*MSTR + kb + 2*tig;
                ah0[0] = *(const uint32_t*)(p);
                ah0[1] = *(const uint32_t*)(p + 8*MSTR);
                ah0[2] = *(const uint32_t*)(p + 8);
                ah0[3] = *(const uint32_t*)(p + 8*MSTR + 8);
                al0[0] = *(const uint32_t*)(q);
                al0[1] = *(const uint32_t*)(q + 8*MSTR);
                al0[2] = *(const uint32_t*)(q + 8);
                al0[3] = *(const uint32_t*)(q + 8*MSTR + 8);
            }
            if (m1v){
                const __nv_bfloat16* p = Ah + (mt1*16 + gid)*MSTR + kb + 2*tig;
                const __nv_bfloat16* q = Al + (mt1*16 + gid)*MSTR + kb + 2*tig;
                ah1[0] = *(const uint32_t*)(p);
                ah1[1] = *(const uint32_t*)(p + 8*MSTR);
                ah1[2] = *(const uint32_t*)(p + 8);
                ah1[3] = *(const uint32_t*)(p + 8*MSTR + 8);
                al1[0] = *(const uint32_t*)(q);
                al1[1] = *(const uint32_t*)(q + 8*MSTR);
                al1[2] = *(const uint32_t*)(q + 8);
                al1[3] = *(const uint32_t*)(q + 8*MSTR + 8);
            }
            #pragma unroll
            for (int nt = 0; nt < 13; nt++){
                const __nv_bfloat16* pb = Bh + (nt*8 + gid)*MSTR + kb + 2*tig;
                const __nv_bfloat16* pl = Bl + (nt*8 + gid)*MSTR + kb + 2*tig;
                uint32_t bh0 = *(const uint32_t*)(pb);
                uint32_t bh1 = *(const uint32_t*)(pb + 8);
                uint32_t bl0 = *(const uint32_t*)(pl);
                uint32_t bl1 = *(const uint32_t*)(pl + 8);
                mma16816(acc[0][nt], ah0, bh0, bh1);
                mma16816(acc[0][nt], ah0, bl0, bl1);
                mma16816(acc[0][nt], al0, bh0, bh1);
                if (m1v){
                    mma16816(acc[1][nt], ah1, bh0, bh1);
                    mma16816(acc[1][nt], ah1, bl0, bl1);
                    mma16816(acc[1][nt], al1, bh0, bh1);
                }
            }
        }
    }

    // ---- epilogue: scale by inv_mqn[j], reduce max/sum over this j-half ----
    #pragma unroll
    for (int s = 0; s < 2; s++){
        int mt = (s == 0) ? mt0 : mt1;
        if (s == 1 && !m1v) continue;
        #pragma unroll
        for (int hh = 0; hh < 2; hh++){
            float mx = -3.402823466e38f, sum = 0.f;
            #pragma unroll
            for (int nt = 0; nt < 13; nt++){
                int n0 = nt*8 + 2*tig;
                float v0 = acc[s][nt][hh*2 + 0] * mqs[n0];
                float v1 = acc[s][nt][hh*2 + 1] * mqs[n0 + 1];
                if (n0     < 100){ mx = fmaxf(mx, v0); sum += v0; }
                if (n0 + 1 < 100){ mx = fmaxf(mx, v1); sum += v1; }
            }
            mx = fmaxf(mx, __shfl_xor_sync(0xffffffffu, mx, 1));
            mx = fmaxf(mx, __shfl_xor_sync(0xffffffffu, mx, 2));
            sum += __shfl_xor_sync(0xffffffffu, sum, 1);
            sum += __shfl_xor_sync(0xffffffffu, sum, 2);
            if (tig == 0){
                int i = mt*16 + gid + hh*8;
                if (i < 200){
                    size_t m = (size_t)b*10240 + (size_t)c*LL + i;
                    g_pmax[jh][m] = mx;
                    g_psum[jh][m] = sum;
                }
            }
        }
    }
}

// ---------------- kernel 5: combine j-halves, apply inv_mpn ----------------
__global__ void k_mpfin(float* __restrict__ out)
{
    int idx = blockIdx.x*256 + threadIdx.x;
    if (idx >= BB*LL*CC) return;
    int b = idx / (LL*CC), m = idx - b*(LL*CC);
    int c = m / LL, i = m - c*LL;
    size_t pi = (size_t)b*10240 + m;
    float invp = g_inv_mpn[((size_t)b*LL + i)*CC + c];
    float mx = fmaxf(g_pmax[0][pi], g_pmax[1][pi]) * invp;
    float sm = (g_psum[0][pi] + g_psum[1][pi]) * invp;
    float* o = out + ((size_t)b*LL + i)*OUTC;
    o[ 50 + c] = mx;
    o[100 + c] = sm * (1.0f/200.0f);
}

// ---------------- launcher -------------------------------------------------
extern "C" void kernel_launch(void* const* d_in, const int* in_sizes, int n_in,
                              void* d_out, int out_size)
{
    const float* q_rep  = (const float*)d_in[0];
    const float* q_last = (const float*)d_in[1];
    const float* q_mask = (const float*)d_in[2];
    const float* d_rep  = (const float*)d_in[3];
    // d_in[4] = d_last (unused by reference)
    const float* d_mask = (const float*)d_in[5];
    const float* fullM  = (const float*)d_in[6];
    const float* mpM    = (const float*)d_in[7];
    const float* attM   = (const float*)d_in[8];
    const float* xattM  = (const float*)d_in[9];
    float* out = (float*)d_out;

    k_prep<<<(CC*KK + 255)/256, 256>>>(fullM, mpM, attM, xattM);
    k_qsplit<<<(BB*LL*KK + 255)/256, 256>>>(q_rep);
    k_norms<<<BB*LL, 512>>>(q_rep, d_rep);
    k_fqn<<<BB, 64>>>(q_last);

    cudaFuncSetAttribute(k_relmatch2, cudaFuncAttributeMaxDynamicSharedMemorySize, RM_SMEM);
    k_relmatch2<<<BB*8, 256, RM_SMEM>>>(q_rep, q_last, q_mask, d_rep, d_mask, out);

    cudaFuncSetAttribute(k_mp_mma, cudaFuncAttributeMaxDynamicSharedMemorySize, MM_SMEM);
    k_mp_mma<<<BB*CC*2, 256, MM_SMEM>>>(d_rep);

    k_mpfin<<<(BB*LL*CC + 255)/256, 256>>>(out);
}

// round 14
// speedup vs baseline: 1.4848x; 1.1604x over previous
#include <cuda_runtime.h>
#include <cuda_bf16.h>
#include <cstdint>

#define BB 32
#define LL 200
#define KK 200
#define CC 50
#define OUTC 250
#define EPSF 1e-6f

// ---------------- device scratch (static allocations are allowed) ----------
__device__ float g_inv_qn[BB*LL];
__device__ float g_inv_dn[BB*LL];
__device__ float g_inv_mqn[BB*LL*CC];   // q under maxpool_M
__device__ float g_inv_mqnT[BB*CC*LL];  // transposed: [(b,c), j]
__device__ float g_inv_mpn[BB*LL*CC];   // d under maxpool_M
__device__ float g_inv_fpn[BB*LL*CC];   // d under full_M
__device__ float g_inv_apn[BB*LL*CC];   // d under att_M
__device__ float g_inv_xpn[BB*LL*CC];   // d under max_att_M
__device__ float g_inv_xqn[BB*LL*CC];   // q under max_att_M
__device__ float g_inv_fqn[BB*CC];      // q_last under full_M
__device__ float g_fullM2T[KK*CC];
__device__ float g_attM2T[KK*CC];
__device__ float g_xattM2T[KK*CC];
__device__ float g_mpM2T[KK*CC];
__device__ float g_mpM2[CC*KK];
// bf16 split of q_rep (hi + lo), built once, reused across all 50 channels
__device__ __nv_bfloat16 g_qh[BB*LL*KK];
__device__ __nv_bfloat16 g_ql[BB*LL*KK];
// maxpool partials: [jhalf][b*10240 + c*200 + i]
__device__ float g_pmax[2][BB*10240];
__device__ float g_psum[2][BB*10240];

// ---------------- warp-level bf16 MMA (generic PTX, sm_80+) ----------------
__device__ __forceinline__ void mma16816(float* d, const uint32_t* a,
                                         uint32_t b0, uint32_t b1){
    asm volatile(
        "mma.sync.aligned.m16n8k16.row.col.f32.bf16.bf16.f32 "
        "{%0,%1,%2,%3}, {%4,%5,%6,%7}, {%8,%9}, {%0,%1,%2,%3};"
        : "+f"(d[0]), "+f"(d[1]), "+f"(d[2]), "+f"(d[3])
        : "r"(a[0]), "r"(a[1]), "r"(a[2]), "r"(a[3]), "r"(b0), "r"(b1));
}

// ---------------- kernel 0: fused setup (prep + qsplit + fqn) --------------
// blocks [0,40): squared/transposed M matrices
// blocks [40,5040): bf16 split of q_rep
// blocks [5040,5072): q_last norms under full_M (self-contained)
__global__ void __launch_bounds__(256) k_setup(
    const float* __restrict__ fullM, const float* __restrict__ mpM,
    const float* __restrict__ attM,  const float* __restrict__ xattM,
    const float* __restrict__ q_rep, const float* __restrict__ q_last)
{
    int bx = blockIdx.x, tid = threadIdx.x;
    if (bx < 40){
        int idx = bx*256 + tid;
        if (idx >= CC*KK) return;
        int c = idx / KK, k = idx - c*KK;
        float fm = fullM[idx];  g_fullM2T[k*CC + c] = fm*fm;
        float am = attM[idx];   g_attM2T [k*CC + c] = am*am;
        float xm = xattM[idx];  g_xattM2T[k*CC + c] = xm*xm;
        float mm = mpM[idx];    g_mpM2T  [k*CC + c] = mm*mm;
        g_mpM2[idx] = mm*mm;
    } else if (bx < 5040){
        int idx = (bx - 40)*256 + tid;
        if (idx >= BB*LL*KK) return;
        float v = q_rep[idx];
        __nv_bfloat16 h = __float2bfloat16(v);
        g_qh[idx] = h;
        g_ql[idx] = __float2bfloat16(v - __bfloat162float(h));
    } else {
        int b = bx - 5040;
        __shared__ float ql[KK];
        for (int k = tid; k < KK; k += 256) ql[k] = q_last[(size_t)b*KK + k];
        __syncthreads();
        int c = tid;
        if (c < CC){
            float s = 0.f;
            for (int k = 0; k < KK; k++){
                float v = ql[k];
                float fm = fullM[(size_t)c*KK + k];
                s += v*v*(fm*fm);
            }
            g_inv_fqn[b*CC + c] = 1.0f / sqrtf(fmaxf(s, EPSF));
        }
    }
}

// ---------------- kernel 1: all per-row inverse norms ----------------------
__global__ void __launch_bounds__(512) k_norms(const float* __restrict__ q_rep,
                                               const float* __restrict__ d_rep)
{
    __shared__ float qr[KK], dr[KK];
    int row = blockIdx.x;                 // b*LL + l
    int tid = threadIdx.x;
    if (tid < KK){ qr[tid] = q_rep[(size_t)row*KK + tid];
                   dr[tid] = d_rep[(size_t)row*KK + tid]; }
    __syncthreads();

    int grp = tid >> 6, c = tid & 63;
    if (grp < 6){
        if (c < CC){
            const float* rv; const float* M2T; float* outp;
            switch (grp){
                case 0:  rv = qr; M2T = g_mpM2T;   outp = g_inv_mqn; break;
                case 1:  rv = qr; M2T = g_xattM2T; outp = g_inv_xqn; break;
                case 2:  rv = dr; M2T = g_mpM2T;   outp = g_inv_mpn; break;
                case 3:  rv = dr; M2T = g_fullM2T; outp = g_inv_fpn; break;
                case 4:  rv = dr; M2T = g_attM2T;  outp = g_inv_apn; break;
                default: rv = dr; M2T = g_xattM2T; outp = g_inv_xpn; break;
            }
            float s = 0.f;
            #pragma unroll 4
            for (int k = 0; k < KK; k++){ float v = rv[k]; s += v*v*M2T[k*CC + c]; }
            float inv = 1.0f / sqrtf(fmaxf(s, EPSF));
            outp[(size_t)row*CC + c] = inv;
            if (grp == 0){
                int b = row / LL, l = row - b*LL;
                g_inv_mqnT[((size_t)b*CC + c)*LL + l] = inv;
            }
        }
    } else if (grp == 6){
        int lane = tid & 31;
        float s = 0.f;
        for (int k = lane; k < KK; k += 32){ float v = qr[k]; s += v*v; }
        #pragma unroll
        for (int off = 16; off; off >>= 1) s += __shfl_xor_sync(0xffffffffu, s, off);
        if (lane == 0) g_inv_qn[row] = 1.0f / sqrtf(fmaxf(s, EPSF));
    } else {
        int lane = tid & 31;
        float s = 0.f;
        for (int k = lane; k < KK; k += 32){ float v = dr[k]; s += v*v; }
        #pragma unroll
        for (int off = 16; off; off >>= 1) s += __shfl_xor_sync(0xffffffffu, s, off);
        if (lane == 0) g_inv_dn[row] = 1.0f / sqrtf(fmaxf(s, EPSF));
    }
}

// ---------------- kernel 3: rel / wq / full / att / max-att ----------------
#define RT 25
#define RKC 40
#define DS_STR 204
#define REL_STR 208
#define WQ_STR 204
#define QS_STR 209
#define MQ_STR 204
#define OFF_DSM   0
#define OFF_REL   (OFF_DSM + RT*DS_STR)
#define OFF_WQ    (OFF_REL + RT*REL_STR)
#define OFF_QSM   (OFF_WQ  + RT*WQ_STR)
#define OFF_QSC   (OFF_QSM + RKC*QS_STR)
#define OFF_QL    (OFF_QSC + 200)
#define OFF_ISC   (OFF_QL  + 200)
#define OFF_IRS   (OFF_ISC + 32)
#define OFF_BJ    (OFF_IRS + 32)
#define RM_FLOATS (OFF_BJ + 32)
#define RM_SMEM   (RM_FLOATS*4)
#define NOUT 15                            // ceil(25*150/256)

__global__ void __launch_bounds__(256) k_relmatch2(
    const float* __restrict__ q_rep, const float* __restrict__ q_last,
    const float* __restrict__ q_mask, const float* __restrict__ d_rep,
    const float* __restrict__ d_mask, float* __restrict__ out)
{
    extern __shared__ float sm[];
    float* dsm    = sm + OFF_DSM;
    float* relsm  = sm + OFF_REL;
    float* wqsm   = sm + OFF_WQ;
    float* qsm    = sm + OFF_QSM;
    float* qscale = sm + OFF_QSC;
    float* qlsm   = sm + OFF_QL;
    float* iscale = sm + OFF_ISC;
    float* irs    = sm + OFF_IRS;
    int*   bjsm   = (int*)(sm + OFF_BJ);

    int b  = blockIdx.x >> 3;
    int it = blockIdx.x & 7;
    int i0g = it * RT;
    int tid = threadIdx.x;
    const float* qb = q_rep + (size_t)b*LL*KK;
    const float* db = d_rep + (size_t)b*LL*KK + (size_t)i0g*KK;

    for (int idx = tid; idx < RT*KK; idx += 256){
        int i = idx / KK, k = idx - i*KK;
        dsm[i*DS_STR + k] = db[idx];
    }
    for (int j = tid; j < LL; j += 256)
        qscale[j] = g_inv_qn[b*LL + j] * q_mask[b*LL + j];
    for (int k = tid; k < KK; k += 256)
        qlsm[k] = q_last[(size_t)b*KK + k];
    if (tid < RT){
        int row = b*LL + i0g + tid;
        iscale[tid] = g_inv_dn[row] * d_mask[row];
    }
    __syncthreads();

    // ---- phase 1: rel GEMM ----
    int ig = tid / 40, jg = tid % 40;
    float acc[5][5];
    #pragma unroll
    for (int r = 0; r < 5; r++)
        #pragma unroll
        for (int jj = 0; jj < 5; jj++) acc[r][jj] = 0.f;

    for (int k0 = 0; k0 < KK; k0 += RKC){
        for (int idx = tid; idx < RKC*LL; idx += 256){
            int j = idx / RKC, kk = idx - j*RKC;
            qsm[kk*QS_STR + j] = qb[(size_t)j*KK + k0 + kk];
        }
        __syncthreads();
        if (tid < 200){
            #pragma unroll 4
            for (int kk = 0; kk < RKC; kk++){
                float a[5], qv[5];
                #pragma unroll
                for (int r = 0; r < 5; r++)  a[r]  = dsm[(ig*5+r)*DS_STR + k0 + kk];
                #pragma unroll
                for (int jj = 0; jj < 5; jj++) qv[jj] = qsm[kk*QS_STR + jg*5 + jj];
                #pragma unroll
                for (int r = 0; r < 5; r++)
                    #pragma unroll
                    for (int jj = 0; jj < 5; jj++) acc[r][jj] += a[r]*qv[jj];
            }
        }
        __syncthreads();
    }
    if (tid < 200){
        #pragma unroll
        for (int r = 0; r < 5; r++){
            int i = ig*5 + r; float isc = iscale[i];
            #pragma unroll
            for (int jj = 0; jj < 5; jj++){
                int j = jg*5 + jj;
                relsm[i*REL_STR + j] = acc[r][jj] * qscale[j] * isc;
            }
        }
    }
    __syncthreads();

    // ---- phase 2: per-row sum + first-occurrence argmax ----
    {
        int w = tid >> 5, lane = tid & 31;
        for (int i = w; i < RT; i += 8){
            float s = 0.f, bv = -3.402823466e38f; int bi = 0;
            for (int j = lane; j < LL; j += 32){
                float v = relsm[i*REL_STR + j];
                s += v;
                if (v > bv){ bv = v; bi = j; }
            }
            #pragma unroll
            for (int off = 16; off; off >>= 1){
                s += __shfl_xor_sync(0xffffffffu, s, off);
                float ov = __shfl_xor_sync(0xffffffffu, bv, off);
                int   oi = __shfl_xor_sync(0xffffffffu, bi, off);
                if (ov > bv || (ov == bv && oi < bi)){ bv = ov; bi = oi; }
            }
            if (lane == 0){ irs[i] = 1.0f / (s + EPSF); bjsm[i] = bi; }
        }
    }
    __syncthreads();

    // ---- phase 3: wq GEMM ----
    if (tid < 250){
        int ig2 = tid / 50, kg = tid % 50;
        float a0[5], a1[5], a2[5], a3[5];
        #pragma unroll
        for (int r = 0; r < 5; r++){ a0[r]=0.f; a1[r]=0.f; a2[r]=0.f; a3[r]=0.f; }
        const float4* qb4 = (const float4*)qb;
        for (int j = 0; j < LL; j++){
            float4 qv = qb4[j*50 + kg];
            #pragma unroll
            for (int r = 0; r < 5; r++){
                float rv = relsm[(ig2*5+r)*REL_STR + j];
                a0[r] += rv*qv.x; a1[r] += rv*qv.y;
                a2[r] += rv*qv.z; a3[r] += rv*qv.w;
            }
        }
        #pragma unroll
        for (int r = 0; r < 5; r++){
            int i = ig2*5 + r; float inv = irs[i];
            float* wp = wqsm + i*WQ_STR + kg*4;
            wp[0] = a0[r]*inv; wp[1] = a1[r]*inv; wp[2] = a2[r]*inv; wp[3] = a3[r]*inv;
        }
    }
    __syncthreads();

    // ---- phase 4: output columns, all operands staged in smem ----
    // mqs reuses relsm (done); m2s reuses qsm (done after phase 1)
    float* mqs = relsm;                    // [RT][MQ_STR]
    float* m2s = qsm;                      // [3][40][50]
    for (int idx = tid; idx < RT*KK; idx += 256){
        int i = idx / KK, k = idx - i*KK;
        mqs[i*MQ_STR + k] = qb[(size_t)bjsm[i]*KK + k];
    }
    __syncthreads();

    float accA[NOUT], accB[NOUT];
    #pragma unroll
    for (int n = 0; n < NOUT; n++){ accA[n] = 0.f; accB[n] = 0.f; }

    for (int k0 = 0; k0 < KK; k0 += 40){
        __syncthreads();                   // previous-chunk reads done
        for (int idx = tid; idx < 3*40*50; idx += 256){
            int m = idx / 2000, r = idx - m*2000;
            int kk = r / 50, c = r - kk*50;
            const float* src = (m == 0) ? g_fullM2T : (m == 1) ? g_attM2T : g_xattM2T;
            m2s[idx] = src[(size_t)(k0 + kk)*CC + c];
        }
        __syncthreads();

        int n = 0;
        for (int idx = tid; idx < RT*150; idx += 256, n++){
            int i = idx / 150, o = idx - i*150;
            int grp = o / 50, c = o - grp*50;
            const float* drow = dsm + i*DS_STR + k0;
            const float* m2p  = m2s + grp*2000 + c;
            if (grp == 0){
                const float* qlp = qlsm + k0;
                float s = accA[n];
                #pragma unroll 4
                for (int kk = 0; kk < 40; kk++)
                    s += drow[kk]*qlp[kk]*m2p[kk*50];
                accA[n] = s;
            } else if (grp == 1){
                const float* wrow = wqsm + i*WQ_STR + k0;
                float sn = accA[n], sq = accB[n];
                #pragma unroll 4
                for (int kk = 0; kk < 40; kk++){
                    float m2 = m2p[kk*50];
                    float wv = wrow[kk];
                    sn += drow[kk]*wv*m2;
                    sq += wv*wv*m2;
                }
                accA[n] = sn; accB[n] = sq;
            } else {
                const float* qrow = mqs + i*MQ_STR + k0;
                float s = accA[n];
                #pragma unroll 4
                for (int kk = 0; kk < 40; kk++)
                    s += drow[kk]*qrow[kk]*m2p[kk*50];
                accA[n] = s;
            }
        }
    }

    {
        int n = 0;
        for (int idx = tid; idx < RT*150; idx += 256, n++){
            int i = idx / 150, o = idx - i*150;
            int grp = o / 50, c = o - grp*50;
            int row = b*LL + i0g + i;
            if (grp == 0){
                out[(size_t)row*OUTC + c] = accA[n] * g_inv_fpn[(size_t)row*CC + c]
                                                     * g_inv_fqn[b*CC + c];
            } else if (grp == 1){
                out[(size_t)row*OUTC + 150 + c] =
                    accA[n] * g_inv_apn[(size_t)row*CC + c]
                            * (1.0f / sqrtf(fmaxf(accB[n], EPSF)));
            } else {
                out[(size_t)row*OUTC + 200 + c] =
                    accA[n] * g_inv_xpn[(size_t)row*CC + c]
                            * g_inv_xqn[(size_t)(b*LL + bjsm[i])*CC + c];
            }
        }
    }
}

// ---------------- kernel 4: maxpool matching via warp MMA (bf16 split) -----
// block = (b, c, jh). 3 passes Ah*Bh + Ah*Bl + Al*Bh, fp32 accum.
// K covered by chunks {64,64,64,16} = 208 (13 k-steps; was 16 -> -18.75%).
#define MSTR 72                            // bf16 per smem row (144 B)
#define SM_AH 0
#define SM_AL (208*MSTR)
#define SM_BH (2*208*MSTR)
#define SM_BL (SM_BH + 104*MSTR)
#define SM_BF16 (SM_BL + 104*MSTR)
#define MM_SMEM (SM_BF16*2 + 104*4)

__global__ void __launch_bounds__(256, 1) k_mp_mma(const float* __restrict__ d_rep)
{
    extern __shared__ __nv_bfloat16 smb[];
    __nv_bfloat16* Ah = smb + SM_AH;
    __nv_bfloat16* Al = smb + SM_AL;
    __nv_bfloat16* Bh = smb + SM_BH;
    __nv_bfloat16* Bl = smb + SM_BL;
    float* mqs = (float*)(smb + SM_BF16);

    int bx = blockIdx.x;
    int jh = bx & 1;
    int c  = (bx >> 1) % CC;
    int b  = bx / (2*CC);
    int tid = threadIdx.x, wid = tid >> 5, lane = tid & 31;
    int gid = lane >> 2, tig = lane & 3;

    const float* db = d_rep + (size_t)b*LL*KK;
    const float* m2 = g_mpM2 + (size_t)c*KK;

    for (int n = tid; n < 104; n += 256)
        mqs[n] = (n < 100) ? g_inv_mqnT[((size_t)b*CC + c)*LL + jh*100 + n] : 0.f;

    float acc[2][13][4];
    #pragma unroll
    for (int s = 0; s < 2; s++)
        #pragma unroll
        for (int nt = 0; nt < 13; nt++)
            #pragma unroll
            for (int r = 0; r < 4; r++) acc[s][nt][r] = 0.f;

    int mt0 = wid, mt1 = wid + 8;
    bool m1v = (mt1 < 13);

    for (int kc = 0; kc < 4; kc++){
        int k0 = kc*64;
        int kwid = (kc == 3) ? 16 : 64;
        int nks  = (kc == 3) ? 1 : 4;
        __syncthreads();
        // fill A (d * M2, bf16 split)
        for (int idx = tid; idx < 208*kwid; idx += 256){
            int r = idx / kwid, kk = idx - r*kwid, gk = k0 + kk;
            float v = 0.f;
            if (r < 200 && gk < 200) v = db[(size_t)r*KK + gk] * m2[gk];
            __nv_bfloat16 h = __float2bfloat16(v);
            Ah[r*MSTR + kk] = h;
            Al[r*MSTR + kk] = __float2bfloat16(v - __bfloat162float(h));
        }
        // fill B from prebuilt q split
        for (int idx = tid; idx < 104*kwid; idx += 256){
            int n = idx / kwid, kk = idx - n*kwid, gk = k0 + kk;
            __nv_bfloat16 h = __float2bfloat16(0.f), l = h;
            if (n < 100 && gk < 200){
                size_t o = ((size_t)b*LL + jh*100 + n)*KK + gk;
                h = g_qh[o]; l = g_ql[o];
            }
            Bh[n*MSTR + kk] = h; Bl[n*MSTR + kk] = l;
        }
        __syncthreads();

        for (int ks = 0; ks < nks; ks++){
            int kb = ks*16;
            uint32_t ah0[4], al0[4], ah1[4], al1[4];
            {
                const __nv_bfloat16* p = Ah + (mt0*16 + gid)*MSTR + kb + 2*tig;
                const __nv_bfloat16* q = Al + (mt0*16 + gid)*MSTR + kb + 2*tig;
                ah0[0] = *(const uint32_t*)(p);
                ah0[1] = *(const uint32_t*)(p + 8*MSTR);
                ah0[2] = *(const uint32_t*)(p + 8);
                ah0[3] = *(const uint32_t*)(p + 8*MSTR + 8);
                al0[0] = *(const uint32_t*)(q);
                al0[1] = *(const uint32_t*)(q + 8*MSTR);
                al0[2] = *(const uint32_t*)(q + 8);
                al0[3] = *(const uint32_t*)(q + 8*MSTR + 8);
            }
            if (m1v){
                const __nv_bfloat16* p = Ah + (mt1*16 + gid)*MSTR + kb + 2*tig;
                const __nv_bfloat16* q = Al + (mt1*16 + gid)*MSTR + kb + 2*tig;
                ah1[0] = *(const uint32_t*)(p);
                ah1[1] = *(const uint32_t*)(p + 8*MSTR);
                ah1[2] = *(const uint32_t*)(p + 8);
                ah1[3] = *(const uint32_t*)(p + 8*MSTR + 8);
                al1[0] = *(const uint32_t*)(q);
                al1[1] = *(const uint32_t*)(q + 8*MSTR);
                al1[2] = *(const uint32_t*)(q + 8);
                al1[3] = *(const uint32_t*)(q + 8*MSTR + 8);
            }
            #pragma unroll
            for (int nt = 0; nt < 13; nt++){
                const __nv_bfloat16* pb = Bh + (nt*8 + gid)*MSTR + kb + 2*tig;
                const __nv_bfloat16* pl = Bl + (nt*8 + gid)*MSTR + kb + 2*tig;
                uint32_t bh0 = *(const uint32_t*)(pb);
                uint32_t bh1 = *(const uint32_t*)(pb + 8);
                uint32_t bl0 = *(const uint32_t*)(pl);
                uint32_t bl1 = *(const uint32_t*)(pl + 8);
                mma16816(acc[0][nt], ah0, bh0, bh1);
                mma16816(acc[0][nt], ah0, bl0, bl1);
                mma16816(acc[0][nt], al0, bh0, bh1);
                if (m1v){
                    mma16816(acc[1][nt], ah1, bh0, bh1);
                    mma16816(acc[1][nt], ah1, bl0, bl1);
                    mma16816(acc[1][nt], al1, bh0, bh1);
                }
            }
        }
    }

    // ---- epilogue: scale by inv_mqn[j], reduce max/sum over this j-half ----
    #pragma unroll
    for (int s = 0; s < 2; s++){
        int mt = (s == 0) ? mt0 : mt1;
        if (s == 1 && !m1v) continue;
        #pragma unroll
        for (int hh = 0; hh < 2; hh++){
            float mx = -3.402823466e38f, sum = 0.f;
            #pragma unroll
            for (int nt = 0; nt < 13; nt++){
                int n0 = nt*8 + 2*tig;
                float v0 = acc[s][nt][hh*2 + 0] * mqs[n0];
                float v1 = acc[s][nt][hh*2 + 1] * mqs[n0 + 1];
                if (n0     < 100){ mx = fmaxf(mx, v0); sum += v0; }
                if (n0 + 1 < 100){ mx = fmaxf(mx, v1); sum += v1; }
            }
            mx = fmaxf(mx, __shfl_xor_sync(0xffffffffu, mx, 1));
            mx = fmaxf(mx, __shfl_xor_sync(0xffffffffu, mx, 2));
            sum += __shfl_xor_sync(0xffffffffu, sum, 1);
            sum += __shfl_xor_sync(0xffffffffu, sum, 2);
            if (tig == 0){
                int i = mt*16 + gid + hh*8;
                if (i < 200){
                    size_t m = (size_t)b*10240 + (size_t)c*LL + i;
                    g_pmax[jh][m] = mx;
                    g_psum[jh][m] = sum;
                }
            }
        }
    }
}

// ---------------- kernel 5: combine j-halves, apply inv_mpn ----------------
__global__ void k_mpfin(float* __restrict__ out)
{
    int idx = blockIdx.x*256 + threadIdx.x;
    if (idx >= BB*LL*CC) return;
    int b = idx / (LL*CC), m = idx - b*(LL*CC);
    int c = m / LL, i = m - c*LL;
    size_t pi = (size_t)b*10240 + m;
    float invp = g_inv_mpn[((size_t)b*LL + i)*CC + c];
    float mx = fmaxf(g_pmax[0][pi], g_pmax[1][pi]) * invp;
    float sm = (g_psum[0][pi] + g_psum[1][pi]) * invp;
    float* o = out + ((size_t)b*LL + i)*OUTC;
    o[ 50 + c] = mx;
    o[100 + c] = sm * (1.0f/200.0f);
}

// ---------------- launcher -------------------------------------------------
extern "C" void kernel_launch(void* const* d_in, const int* in_sizes, int n_in,
                              void* d_out, int out_size)
{
    const float* q_rep  = (const float*)d_in[0];
    const float* q_last = (const float*)d_in[1];
    const float* q_mask = (const float*)d_in[2];
    const float* d_rep  = (const float*)d_in[3];
    // d_in[4] = d_last (unused by reference)
    const float* d_mask = (const float*)d_in[5];
    const float* fullM  = (const float*)d_in[6];
    const float* mpM    = (const float*)d_in[7];
    const float* attM   = (const float*)d_in[8];
    const float* xattM  = (const float*)d_in[9];
    float* out = (float*)d_out;

    k_setup<<<5072, 256>>>(fullM, mpM, attM, xattM, q_rep, q_last);
    k_norms<<<BB*LL, 512>>>(q_rep, d_rep);

    cudaFuncSetAttribute(k_relmatch2, cudaFuncAttributeMaxDynamicSharedMemorySize, RM_SMEM);
    k_relmatch2<<<BB*8, 256, RM_SMEM>>>(q_rep, q_last, q_mask, d_rep, d_mask, out);

    cudaFuncSetAttribute(k_mp_mma, cudaFuncAttributeMaxDynamicSharedMemorySize, MM_SMEM);
    k_mp_mma<<<BB*CC*2, 256, MM_SMEM>>>(d_rep);

    k_mpfin<<<(BB*LL*CC + 255)/256, 256>>>(out);
}

// round 16
// speedup vs baseline: 1.7263x; 1.1626x over previous
#include <cuda_runtime.h>
#include <cuda_bf16.h>
#include <cstdint>

#define BB 32
#define LL 200
#define KK 200
#define CC 50
#define OUTC 250
#define EPSF 1e-6f

// ---------------- device scratch (static allocations are allowed) ----------
__device__ float g_inv_qn[BB*LL];
__device__ float g_inv_dn[BB*LL];
__device__ float g_inv_mqn[BB*LL*CC];   // q under maxpool_M
__device__ float g_inv_mqnT[BB*CC*LL];  // transposed: [(b,c), j]
__device__ float g_inv_mpn[BB*LL*CC];   // d under maxpool_M
__device__ float g_inv_fpn[BB*LL*CC];   // d under full_M
__device__ float g_inv_apn[BB*LL*CC];   // d under att_M
__device__ float g_inv_xpn[BB*LL*CC];   // d under max_att_M
__device__ float g_inv_xqn[BB*LL*CC];   // q under max_att_M
__device__ float g_inv_fqn[BB*CC];      // q_last under full_M
__device__ float g_fullM2T[KK*CC];
__device__ float g_attM2T[KK*CC];
__device__ float g_xattM2T[KK*CC];
__device__ float g_mpM2T[KK*CC];
__device__ float g_mpM2[CC*KK];
// bf16 split of q_rep (hi + lo), built once, reused across all 50 channels
__device__ __nv_bfloat16 g_qh[BB*LL*KK];
__device__ __nv_bfloat16 g_ql[BB*LL*KK];
// maxpool partials: [jhalf][b*10240 + c*200 + i]
__device__ float g_pmax[2][BB*10240];
__device__ float g_psum[2][BB*10240];

// ---------------- warp-level MMA + ldmatrix (generic PTX) ------------------
__device__ __forceinline__ void mma16816(float* d, const uint32_t* a,
                                         uint32_t b0, uint32_t b1){
    asm volatile(
        "mma.sync.aligned.m16n8k16.row.col.f32.bf16.bf16.f32 "
        "{%0,%1,%2,%3}, {%4,%5,%6,%7}, {%8,%9}, {%0,%1,%2,%3};"
        : "+f"(d[0]), "+f"(d[1]), "+f"(d[2]), "+f"(d[3])
        : "r"(a[0]), "r"(a[1]), "r"(a[2]), "r"(a[3]), "r"(b0), "r"(b1));
}
__device__ __forceinline__ void ldm_x4(uint32_t* r, uint32_t addr){
    asm volatile("ldmatrix.sync.aligned.m8n8.x4.shared.b16 {%0,%1,%2,%3}, [%4];"
        : "=r"(r[0]), "=r"(r[1]), "=r"(r[2]), "=r"(r[3]) : "r"(addr));
}
__device__ __forceinline__ void ldm_x2(uint32_t* r, uint32_t addr){
    asm volatile("ldmatrix.sync.aligned.m8n8.x2.shared.b16 {%0,%1}, [%2];"
        : "=r"(r[0]), "=r"(r[1]) : "r"(addr));
}
__device__ __forceinline__ uint32_t smem_u32(const void* p){
    uint32_t a;
    asm("{ .reg .u64 t; cvta.to.shared.u64 t, %1; cvt.u32.u64 %0, t; }"
        : "=r"(a) : "l"(p));
    return a;
}

// ---------------- kernel 0: fused setup (prep + qsplit + fqn) --------------
__global__ void __launch_bounds__(256) k_setup(
    const float* __restrict__ fullM, const float* __restrict__ mpM,
    const float* __restrict__ attM,  const float* __restrict__ xattM,
    const float* __restrict__ q_rep, const float* __restrict__ q_last)
{
    int bx = blockIdx.x, tid = threadIdx.x;
    if (bx < 40){
        int idx = bx*256 + tid;
        if (idx >= CC*KK) return;
        int c = idx / KK, k = idx - c*KK;
        float fm = fullM[idx];  g_fullM2T[k*CC + c] = fm*fm;
        float am = attM[idx];   g_attM2T [k*CC + c] = am*am;
        float xm = xattM[idx];  g_xattM2T[k*CC + c] = xm*xm;
        float mm = mpM[idx];    g_mpM2T  [k*CC + c] = mm*mm;
        g_mpM2[idx] = mm*mm;
    } else if (bx < 5040){
        int idx = (bx - 40)*256 + tid;
        if (idx >= BB*LL*KK) return;
        float v = q_rep[idx];
        __nv_bfloat16 h = __float2bfloat16(v);
        g_qh[idx] = h;
        g_ql[idx] = __float2bfloat16(v - __bfloat162float(h));
    } else {
        int b = bx - 5040;
        __shared__ float ql[KK];
        for (int k = tid; k < KK; k += 256) ql[k] = q_last[(size_t)b*KK + k];
        __syncthreads();
        int c = tid;
        if (c < CC){
            float s = 0.f;
            for (int k = 0; k < KK; k++){
                float v = ql[k];
                float fm = fullM[(size_t)c*KK + k];
                s += v*v*(fm*fm);
            }
            g_inv_fqn[b*CC + c] = 1.0f / sqrtf(fmaxf(s, EPSF));
        }
    }
}

// ---------------- kernel 1: all per-row inverse norms ----------------------
__global__ void __launch_bounds__(512) k_norms(const float* __restrict__ q_rep,
                                               const float* __restrict__ d_rep)
{
    __shared__ float qr[KK], dr[KK];
    int row = blockIdx.x;                 // b*LL + l
    int tid = threadIdx.x;
    if (tid < KK){ qr[tid] = q_rep[(size_t)row*KK + tid];
                   dr[tid] = d_rep[(size_t)row*KK + tid]; }
    __syncthreads();

    int grp = tid >> 6, c = tid & 63;
    if (grp < 6){
        if (c < CC){
            const float* rv; const float* M2T; float* outp;
            switch (grp){
                case 0:  rv = qr; M2T = g_mpM2T;   outp = g_inv_mqn; break;
                case 1:  rv = qr; M2T = g_xattM2T; outp = g_inv_xqn; break;
                case 2:  rv = dr; M2T = g_mpM2T;   outp = g_inv_mpn; break;
                case 3:  rv = dr; M2T = g_fullM2T; outp = g_inv_fpn; break;
                case 4:  rv = dr; M2T = g_attM2T;  outp = g_inv_apn; break;
                default: rv = dr; M2T = g_xattM2T; outp = g_inv_xpn; break;
            }
            float s = 0.f;
            #pragma unroll 4
            for (int k = 0; k < KK; k++){ float v = rv[k]; s += v*v*M2T[k*CC + c]; }
            float inv = 1.0f / sqrtf(fmaxf(s, EPSF));
            outp[(size_t)row*CC + c] = inv;
            if (grp == 0){
                int b = row / LL, l = row - b*LL;
                g_inv_mqnT[((size_t)b*CC + c)*LL + l] = inv;
            }
        }
    } else if (grp == 6){
        int lane = tid & 31;
        float s = 0.f;
        for (int k = lane; k < KK; k += 32){ float v = qr[k]; s += v*v; }
        #pragma unroll
        for (int off = 16; off; off >>= 1) s += __shfl_xor_sync(0xffffffffu, s, off);
        if (lane == 0) g_inv_qn[row] = 1.0f / sqrtf(fmaxf(s, EPSF));
    } else {
        int lane = tid & 31;
        float s = 0.f;
        for (int k = lane; k < KK; k += 32){ float v = dr[k]; s += v*v; }
        #pragma unroll
        for (int off = 16; off; off >>= 1) s += __shfl_xor_sync(0xffffffffu, s, off);
        if (lane == 0) g_inv_dn[row] = 1.0f / sqrtf(fmaxf(s, EPSF));
    }
}

// ---------------- kernel 3: rel / wq / full / att / max-att ----------------
#define RT 25
#define RKC 40
#define DS_STR 204
#define REL_STR 208
#define WQ_STR 204
#define QS_STR 209
#define MQ_STR 204
#define OFF_DSM   0
#define OFF_REL   (OFF_DSM + RT*DS_STR)
#define OFF_WQ    (OFF_REL + RT*REL_STR)
#define OFF_QSM   (OFF_WQ  + RT*WQ_STR)
#define OFF_QSC   (OFF_QSM + RKC*QS_STR)
#define OFF_QL    (OFF_QSC + 200)
#define OFF_ISC   (OFF_QL  + 200)
#define OFF_IRS   (OFF_ISC + 32)
#define OFF_BJ    (OFF_IRS + 32)
#define RM_FLOATS (OFF_BJ + 32)
#define RM_SMEM   (RM_FLOATS*4)
#define NOUT 15

__global__ void __launch_bounds__(256) k_relmatch2(
    const float* __restrict__ q_rep, const float* __restrict__ q_last,
    const float* __restrict__ q_mask, const float* __restrict__ d_rep,
    const float* __restrict__ d_mask, float* __restrict__ out)
{
    extern __shared__ float sm[];
    float* dsm    = sm + OFF_DSM;
    float* relsm  = sm + OFF_REL;
    float* wqsm   = sm + OFF_WQ;
    float* qsm    = sm + OFF_QSM;
    float* qscale = sm + OFF_QSC;
    float* qlsm   = sm + OFF_QL;
    float* iscale = sm + OFF_ISC;
    float* irs    = sm + OFF_IRS;
    int*   bjsm   = (int*)(sm + OFF_BJ);

    int b  = blockIdx.x >> 3;
    int it = blockIdx.x & 7;
    int i0g = it * RT;
    int tid = threadIdx.x;
    const float* qb = q_rep + (size_t)b*LL*KK;
    const float* db = d_rep + (size_t)b*LL*KK + (size_t)i0g*KK;

    for (int idx = tid; idx < RT*KK; idx += 256){
        int i = idx / KK, k = idx - i*KK;
        dsm[i*DS_STR + k] = db[idx];
    }
    for (int j = tid; j < LL; j += 256)
        qscale[j] = g_inv_qn[b*LL + j] * q_mask[b*LL + j];
    for (int k = tid; k < KK; k += 256)
        qlsm[k] = q_last[(size_t)b*KK + k];
    if (tid < RT){
        int row = b*LL + i0g + tid;
        iscale[tid] = g_inv_dn[row] * d_mask[row];
    }
    __syncthreads();

    // ---- phase 1: rel GEMM ----
    int ig = tid / 40, jg = tid % 40;
    float acc[5][5];
    #pragma unroll
    for (int r = 0; r < 5; r++)
        #pragma unroll
        for (int jj = 0; jj < 5; jj++) acc[r][jj] = 0.f;

    for (int k0 = 0; k0 < KK; k0 += RKC){
        for (int idx = tid; idx < RKC*LL; idx += 256){
            int j = idx / RKC, kk = idx - j*RKC;
            qsm[kk*QS_STR + j] = qb[(size_t)j*KK + k0 + kk];
        }
        __syncthreads();
        if (tid < 200){
            #pragma unroll 4
            for (int kk = 0; kk < RKC; kk++){
                float a[5], qv[5];
                #pragma unroll
                for (int r = 0; r < 5; r++)  a[r]  = dsm[(ig*5+r)*DS_STR + k0 + kk];
                #pragma unroll
                for (int jj = 0; jj < 5; jj++) qv[jj] = qsm[kk*QS_STR + jg*5 + jj];
                #pragma unroll
                for (int r = 0; r < 5; r++)
                    #pragma unroll
                    for (int jj = 0; jj < 5; jj++) acc[r][jj] += a[r]*qv[jj];
            }
        }
        __syncthreads();
    }
    if (tid < 200){
        #pragma unroll
        for (int r = 0; r < 5; r++){
            int i = ig*5 + r; float isc = iscale[i];
            #pragma unroll
            for (int jj = 0; jj < 5; jj++){
                int j = jg*5 + jj;
                relsm[i*REL_STR + j] = acc[r][jj] * qscale[j] * isc;
            }
        }
    }
    __syncthreads();

    // ---- phase 2: per-row sum + first-occurrence argmax ----
    {
        int w = tid >> 5, lane = tid & 31;
        for (int i = w; i < RT; i += 8){
            float s = 0.f, bv = -3.402823466e38f; int bi = 0;
            for (int j = lane; j < LL; j += 32){
                float v = relsm[i*REL_STR + j];
                s += v;
                if (v > bv){ bv = v; bi = j; }
            }
            #pragma unroll
            for (int off = 16; off; off >>= 1){
                s += __shfl_xor_sync(0xffffffffu, s, off);
                float ov = __shfl_xor_sync(0xffffffffu, bv, off);
                int   oi = __shfl_xor_sync(0xffffffffu, bi, off);
                if (ov > bv || (ov == bv && oi < bi)){ bv = ov; bi = oi; }
            }
            if (lane == 0){ irs[i] = 1.0f / (s + EPSF); bjsm[i] = bi; }
        }
    }
    __syncthreads();

    // ---- phase 3: wq GEMM ----
    if (tid < 250){
        int ig2 = tid / 50, kg = tid % 50;
        float a0[5], a1[5], a2[5], a3[5];
        #pragma unroll
        for (int r = 0; r < 5; r++){ a0[r]=0.f; a1[r]=0.f; a2[r]=0.f; a3[r]=0.f; }
        const float4* qb4 = (const float4*)qb;
        for (int j = 0; j < LL; j++){
            float4 qv = qb4[j*50 + kg];
            #pragma unroll
            for (int r = 0; r < 5; r++){
                float rv = relsm[(ig2*5+r)*REL_STR + j];
                a0[r] += rv*qv.x; a1[r] += rv*qv.y;
                a2[r] += rv*qv.z; a3[r] += rv*qv.w;
            }
        }
        #pragma unroll
        for (int r = 0; r < 5; r++){
            int i = ig2*5 + r; float inv = irs[i];
            float* wp = wqsm + i*WQ_STR + kg*4;
            wp[0] = a0[r]*inv; wp[1] = a1[r]*inv; wp[2] = a2[r]*inv; wp[3] = a3[r]*inv;
        }
    }
    __syncthreads();

    // ---- phase 4: output columns, all operands staged in smem ----
    float* mqs = relsm;                    // [RT][MQ_STR]
    float* m2s = qsm;                      // [3][40][50]
    for (int idx = tid; idx < RT*KK; idx += 256){
        int i = idx / KK, k = idx - i*KK;
        mqs[i*MQ_STR + k] = qb[(size_t)bjsm[i]*KK + k];
    }
    __syncthreads();

    float accA[NOUT], accB[NOUT];
    #pragma unroll
    for (int n = 0; n < NOUT; n++){ accA[n] = 0.f; accB[n] = 0.f; }

    for (int k0 = 0; k0 < KK; k0 += 40){
        __syncthreads();
        for (int idx = tid; idx < 3*40*50; idx += 256){
            int m = idx / 2000, r = idx - m*2000;
            int kk = r / 50, c = r - kk*50;
            const float* src = (m == 0) ? g_fullM2T : (m == 1) ? g_attM2T : g_xattM2T;
            m2s[idx] = src[(size_t)(k0 + kk)*CC + c];
        }
        __syncthreads();

        int n = 0;
        for (int idx = tid; idx < RT*150; idx += 256, n++){
            int i = idx / 150, o = idx - i*150;
            int grp = o / 50, c = o - grp*50;
            const float* drow = dsm + i*DS_STR + k0;
            const float* m2p  = m2s + grp*2000 + c;
            if (grp == 0){
                const float* qlp = qlsm + k0;
                float s = accA[n];
                #pragma unroll 4
                for (int kk = 0; kk < 40; kk++)
                    s += drow[kk]*qlp[kk]*m2p[kk*50];
                accA[n] = s;
            } else if (grp == 1){
                const float* wrow = wqsm + i*WQ_STR + k0;
                float sn = accA[n], sq = accB[n];
                #pragma unroll 4
                for (int kk = 0; kk < 40; kk++){
                    float m2 = m2p[kk*50];
                    float wv = wrow[kk];
                    sn += drow[kk]*wv*m2;
                    sq += wv*wv*m2;
                }
                accA[n] = sn; accB[n] = sq;
            } else {
                const float* qrow = mqs + i*MQ_STR + k0;
                float s = accA[n];
                #pragma unroll 4
                for (int kk = 0; kk < 40; kk++)
                    s += drow[kk]*qrow[kk]*m2p[kk*50];
                accA[n] = s;
            }
        }
    }

    {
        int n = 0;
        for (int idx = tid; idx < RT*150; idx += 256, n++){
            int i = idx / 150, o = idx - i*150;
            int grp = o / 50, c = o - grp*50;
            int row = b*LL + i0g + i;
            if (grp == 0){
                out[(size_t)row*OUTC + c] = accA[n] * g_inv_fpn[(size_t)row*CC + c]
                                                     * g_inv_fqn[b*CC + c];
            } else if (grp == 1){
                out[(size_t)row*OUTC + 150 + c] =
                    accA[n] * g_inv_apn[(size_t)row*CC + c]
                            * (1.0f / sqrtf(fmaxf(accB[n], EPSF)));
            } else {
                out[(size_t)row*OUTC + 200 + c] =
                    accA[n] * g_inv_xpn[(size_t)row*CC + c]
                            * g_inv_xqn[(size_t)(b*LL + bjsm[i])*CC + c];
            }
        }
    }
}

// ---------------- kernel 4: maxpool matching — ldmatrix + 512 threads ------
// block = (b, c, jh); 512 threads = 16 warps; warps 0-12 each own ONE m16
// tile (13 tiles cover 208 rows), warps 13-15 help fills only.
// Frags via ldmatrix (x4 for A hi/lo, x2 for B hi/lo); 3 bf16-split passes.
// K chunks {64,64,64,16} = 13 k-steps.
#define MSTR 72                            // bf16 per smem row (144 B)
#define SM_AH 0
#define SM_AL (208*MSTR)
#define SM_BH (2*208*MSTR)
#define SM_BL (SM_BH + 104*MSTR)
#define SM_BF16 (SM_BL + 104*MSTR)
#define MM_SMEM (SM_BF16*2 + 104*4)

__global__ void __launch_bounds__(512, 1) k_mp_mma(const float* __restrict__ d_rep)
{
    extern __shared__ __nv_bfloat16 smb[];
    __nv_bfloat16* Ah = smb + SM_AH;
    __nv_bfloat16* Al = smb + SM_AL;
    __nv_bfloat16* Bh = smb + SM_BH;
    __nv_bfloat16* Bl = smb + SM_BL;
    float* mqs = (float*)(smb + SM_BF16);
    uint32_t sbase = smem_u32(smb);

    int bx = blockIdx.x;
    int jh = bx & 1;
    int c  = (bx >> 1) % CC;
    int b  = bx / (2*CC);
    int tid = threadIdx.x, wid = tid >> 5, lane = tid & 31;
    int gid = lane >> 2, tig = lane & 3;

    const float* db = d_rep + (size_t)b*LL*KK;
    const float* m2 = g_mpM2 + (size_t)c*KK;

    for (int n = tid; n < 104; n += 512)
        mqs[n] = (n < 100) ? g_inv_mqnT[((size_t)b*CC + c)*LL + jh*100 + n] : 0.f;

    float acc[13][4];
    #pragma unroll
    for (int nt = 0; nt < 13; nt++)
        #pragma unroll
        for (int r = 0; r < 4; r++) acc[nt][r] = 0.f;

    bool mmawarp = (wid < 13);
    // ldmatrix address components (bytes): A row = wid*16 + (lane&15),
    // col-byte = (lane>>4)*16; B row = lane&7, col-byte = ((lane>>3)&1)*16.
    uint32_t a_row_off = (uint32_t)((wid*16 + (lane & 15))*MSTR*2 + ((lane >> 4)*16));
    uint32_t b_row_off = (uint32_t)((lane & 7)*MSTR*2 + (((lane >> 3) & 1)*16));

    for (int kc = 0; kc < 4; kc++){
        int k0 = kc*64;
        int kwid = (kc == 3) ? 16 : 64;
        int nks  = (kc == 3) ? 1 : 4;
        __syncthreads();
        // fill A (d * M2, bf16 split)
        for (int idx = tid; idx < 208*kwid; idx += 512){
            int r = idx / kwid, kk = idx - r*kwid, gk = k0 + kk;
            float v = 0.f;
            if (r < 200 && gk < 200) v = db[(size_t)r*KK + gk] * m2[gk];
            __nv_bfloat16 h = __float2bfloat16(v);
            Ah[r*MSTR + kk] = h;
            Al[r*MSTR + kk] = __float2bfloat16(v - __bfloat162float(h));
        }
        // fill B from prebuilt q split
        for (int idx = tid; idx < 104*kwid; idx += 512){
            int n = idx / kwid, kk = idx - n*kwid, gk = k0 + kk;
            __nv_bfloat16 h = __float2bfloat16(0.f), l = h;
            if (n < 100 && gk < 200){
                size_t o = ((size_t)b*LL + jh*100 + n)*KK + gk;
                h = g_qh[o]; l = g_ql[o];
            }
            Bh[n*MSTR + kk] = h; Bl[n*MSTR + kk] = l;
        }
        __syncthreads();

        if (mmawarp){
            for (int ks = 0; ks < nks; ks++){
                uint32_t kbb = (uint32_t)(ks*32);          // k-step byte offset
                uint32_t ah[4], al[4];
                ldm_x4(ah, sbase + (uint32_t)(SM_AH*2) + a_row_off + kbb);
                ldm_x4(al, sbase + (uint32_t)(SM_AL*2) + a_row_off + kbb);
                #pragma unroll
                for (int nt = 0; nt < 13; nt++){
                    uint32_t bo = (uint32_t)(nt*8*MSTR*2) + b_row_off + kbb;
                    uint32_t bh[2], bl[2];
                    ldm_x2(bh, sbase + (uint32_t)(SM_BH*2) + bo);
                    ldm_x2(bl, sbase + (uint32_t)(SM_BL*2) + bo);
                    mma16816(acc[nt], ah, bh[0], bh[1]);
                    mma16816(acc[nt], ah, bl[0], bl[1]);
                    mma16816(acc[nt], al, bh[0], bh[1]);
                }
            }
        }
    }

    // ---- epilogue: scale by inv_mqn[j], reduce max/sum over this j-half ----
    if (mmawarp){
        #pragma unroll
        for (int hh = 0; hh < 2; hh++){
            float mx = -3.402823466e38f, sum = 0.f;
            #pragma unroll
            for (int nt = 0; nt < 13; nt++){
                int n0 = nt*8 + 2*tig;
                float v0 = acc[nt][hh*2 + 0] * mqs[n0];
                float v1 = acc[nt][hh*2 + 1] * mqs[n0 + 1];
                if (n0     < 100){ mx = fmaxf(mx, v0); sum += v0; }
                if (n0 + 1 < 100){ mx = fmaxf(mx, v1); sum += v1; }
            }
            mx = fmaxf(mx, __shfl_xor_sync(0xffffffffu, mx, 1));
            mx = fmaxf(mx, __shfl_xor_sync(0xffffffffu, mx, 2));
            sum += __shfl_xor_sync(0xffffffffu, sum, 1);
            sum += __shfl_xor_sync(0xffffffffu, sum, 2);
            if (tig == 0){
                int i = wid*16 + gid + hh*8;
                if (i < 200){
                    size_t m = (size_t)b*10240 + (size_t)c*LL + i;
                    g_pmax[jh][m] = mx;
                    g_psum[jh][m] = sum;
                }
            }
        }
    }
}

// ---------------- kernel 5: combine j-halves, apply inv_mpn ----------------
__global__ void k_mpfin(float* __restrict__ out)
{
    int idx = blockIdx.x*256 + threadIdx.x;
    if (idx >= BB*LL*CC) return;
    int b = idx / (LL*CC), m = idx - b*(LL*CC);
    int c = m / LL, i = m - c*LL;
    size_t pi = (size_t)b*10240 + m;
    float invp = g_inv_mpn[((size_t)b*LL + i)*CC + c];
    float mx = fmaxf(g_pmax[0][pi], g_pmax[1][pi]) * invp;
    float sm = (g_psum[0][pi] + g_psum[1][pi]) * invp;
    float* o = out + ((size_t)b*LL + i)*OUTC;
    o[ 50 + c] = mx;
    o[100 + c] = sm * (1.0f/200.0f);
}

// ---------------- launcher -------------------------------------------------
extern "C" void kernel_launch(void* const* d_in, const int* in_sizes, int n_in,
                              void* d_out, int out_size)
{
    const float* q_rep  = (const float*)d_in[0];
    const float* q_last = (const float*)d_in[1];
    const float* q_mask = (const float*)d_in[2];
    const float* d_rep  = (const float*)d_in[3];
    // d_in[4] = d_last (unused by reference)
    const float* d_mask = (const float*)d_in[5];
    const float* fullM  = (const float*)d_in[6];
    const float* mpM    = (const float*)d_in[7];
    const float* attM   = (const float*)d_in[8];
    const float* xattM  = (const float*)d_in[9];
    float* out = (float*)d_out;

    k_setup<<<5072, 256>>>(fullM, mpM, attM, xattM, q_rep, q_last);
    k_norms<<<BB*LL, 512>>>(q_rep, d_rep);

    cudaFuncSetAttribute(k_relmatch2, cudaFuncAttributeMaxDynamicSharedMemorySize, RM_SMEM);
    k_relmatch2<<<BB*8, 256, RM_SMEM>>>(q_rep, q_last, q_mask, d_rep, d_mask, out);

    cudaFuncSetAttribute(k_mp_mma, cudaFuncAttributeMaxDynamicSharedMemorySize, MM_SMEM);
    k_mp_mma<<<BB*CC*2, 512, MM_SMEM>>>(d_rep);

    k_mpfin<<<(BB*LL*CC + 255)/256, 256>>>(out);
}

// round 17
// speedup vs baseline: 2.0955x; 1.2139x over previous
#include <cuda_runtime.h>
#include <cuda_bf16.h>
#include <cstdint>

#define BB 32
#define LL 200
#define KK 200
#define CC 50
#define OUTC 250
#define EPSF 1e-6f

// ---------------- device scratch (static allocations are allowed) ----------
__device__ float g_inv_qn[BB*LL];
__device__ float g_inv_dn[BB*LL];
__device__ float g_inv_mqn[BB*LL*CC];   // q under maxpool_M
__device__ float g_inv_mqnT[BB*CC*LL];  // transposed: [(b,c), j]
__device__ float g_inv_mpn[BB*LL*CC];   // d under maxpool_M
__device__ float g_inv_fpn[BB*LL*CC];   // d under full_M
__device__ float g_inv_apn[BB*LL*CC];   // d under att_M
__device__ float g_inv_xpn[BB*LL*CC];   // d under max_att_M
__device__ float g_inv_xqn[BB*LL*CC];   // q under max_att_M
__device__ float g_inv_fqn[BB*CC];      // q_last under full_M
__device__ float g_fullM2T[KK*CC];
__device__ float g_attM2T[KK*CC];
__device__ float g_xattM2T[KK*CC];
__device__ float g_mpM2T[KK*CC];
__device__ float g_mpM2[CC*KK];
// bf16 truncation split of d_rep (hi + lo), built once (c-independent A side)
__device__ __nv_bfloat16 g_dh[BB*LL*KK];
__device__ __nv_bfloat16 g_dl[BB*LL*KK];
// maxpool partials: [jhalf][b*10240 + c*200 + i]
__device__ float g_pmax[2][BB*10240];
__device__ float g_psum[2][BB*10240];

// ---------------- warp-level MMA + ldmatrix (generic PTX) ------------------
__device__ __forceinline__ void mma16816(float* d, const uint32_t* a,
                                         uint32_t b0, uint32_t b1){
    asm volatile(
        "mma.sync.aligned.m16n8k16.row.col.f32.bf16.bf16.f32 "
        "{%0,%1,%2,%3}, {%4,%5,%6,%7}, {%8,%9}, {%0,%1,%2,%3};"
        : "+f"(d[0]), "+f"(d[1]), "+f"(d[2]), "+f"(d[3])
        : "r"(a[0]), "r"(a[1]), "r"(a[2]), "r"(a[3]), "r"(b0), "r"(b1));
}
__device__ __forceinline__ void ldm_x4(uint32_t* r, uint32_t addr){
    asm volatile("ldmatrix.sync.aligned.m8n8.x4.shared.b16 {%0,%1,%2,%3}, [%4];"
        : "=r"(r[0]), "=r"(r[1]), "=r"(r[2]), "=r"(r[3]) : "r"(addr));
}
__device__ __forceinline__ void ldm_x2(uint32_t* r, uint32_t addr){
    asm volatile("ldmatrix.sync.aligned.m8n8.x2.shared.b16 {%0,%1}, [%2];"
        : "=r"(r[0]), "=r"(r[1]) : "r"(addr));
}
__device__ __forceinline__ uint32_t smem_u32(const void* p){
    uint32_t a;
    asm("{ .reg .u64 t; cvta.to.shared.u64 t, %1; cvt.u32.u64 %0, t; }"
        : "=r"(a) : "l"(p));
    return a;
}

// ---------------- kernel 0: fused setup (prep + dsplit + fqn) --------------
// blocks [0,40): squared/transposed M matrices
// blocks [40,1290): bf16 trunc split of d_rep (4 elems/thread)
// blocks [1290,1322): q_last norms under full_M
__global__ void __launch_bounds__(256) k_setup(
    const float* __restrict__ fullM, const float* __restrict__ mpM,
    const float* __restrict__ attM,  const float* __restrict__ xattM,
    const float* __restrict__ d_rep, const float* __restrict__ q_last)
{
    int bx = blockIdx.x, tid = threadIdx.x;
    if (bx < 40){
        int idx = bx*256 + tid;
        if (idx >= CC*KK) return;
        int c = idx / KK, k = idx - c*KK;
        float fm = fullM[idx];  g_fullM2T[k*CC + c] = fm*fm;
        float am = attM[idx];   g_attM2T [k*CC + c] = am*am;
        float xm = xattM[idx];  g_xattM2T[k*CC + c] = xm*xm;
        float mm = mpM[idx];    g_mpM2T  [k*CC + c] = mm*mm;
        g_mpM2[idx] = mm*mm;
    } else if (bx < 1290){
        int base = (bx - 40)*1024 + tid*4;        // 1250*1024 == BB*LL*KK exactly
        float4 v = *(const float4*)(d_rep + base);
        uint32_t u0 = __float_as_uint(v.x), u1 = __float_as_uint(v.y);
        uint32_t u2 = __float_as_uint(v.z), u3 = __float_as_uint(v.w);
        float l0 = v.x - __uint_as_float(u0 & 0xffff0000u);
        float l1 = v.y - __uint_as_float(u1 & 0xffff0000u);
        float l2 = v.z - __uint_as_float(u2 & 0xffff0000u);
        float l3 = v.w - __uint_as_float(u3 & 0xffff0000u);
        uint2 hp, lp;
        hp.x = __byte_perm(u0, u1, 0x7632);
        hp.y = __byte_perm(u2, u3, 0x7632);
        lp.x = __byte_perm(__float_as_uint(l0), __float_as_uint(l1), 0x7632);
        lp.y = __byte_perm(__float_as_uint(l2), __float_as_uint(l3), 0x7632);
        *(uint2*)(g_dh + base) = hp;
        *(uint2*)(g_dl + base) = lp;
    } else {
        int b = bx - 1290;
        __shared__ float ql[KK];
        for (int k = tid; k < KK; k += 256) ql[k] = q_last[(size_t)b*KK + k];
        __syncthreads();
        int c = tid;
        if (c < CC){
            float s = 0.f;
            for (int k = 0; k < KK; k++){
                float v = ql[k];
                float fm = fullM[(size_t)c*KK + k];
                s += v*v*(fm*fm);
            }
            g_inv_fqn[b*CC + c] = 1.0f / sqrtf(fmaxf(s, EPSF));
        }
    }
}

// ---------------- kernel 1: all per-row inverse norms ----------------------
__global__ void __launch_bounds__(512) k_norms(const float* __restrict__ q_rep,
                                               const float* __restrict__ d_rep)
{
    __shared__ float qr[KK], dr[KK];
    int row = blockIdx.x;                 // b*LL + l
    int tid = threadIdx.x;
    if (tid < KK){ qr[tid] = q_rep[(size_t)row*KK + tid];
                   dr[tid] = d_rep[(size_t)row*KK + tid]; }
    __syncthreads();

    int grp = tid >> 6, c = tid & 63;
    if (grp < 6){
        if (c < CC){
            const float* rv; const float* M2T; float* outp;
            switch (grp){
                case 0:  rv = qr; M2T = g_mpM2T;   outp = g_inv_mqn; break;
                case 1:  rv = qr; M2T = g_xattM2T; outp = g_inv_xqn; break;
                case 2:  rv = dr; M2T = g_mpM2T;   outp = g_inv_mpn; break;
                case 3:  rv = dr; M2T = g_fullM2T; outp = g_inv_fpn; break;
                case 4:  rv = dr; M2T = g_attM2T;  outp = g_inv_apn; break;
                default: rv = dr; M2T = g_xattM2T; outp = g_inv_xpn; break;
            }
            float s = 0.f;
            #pragma unroll 4
            for (int k = 0; k < KK; k++){ float v = rv[k]; s += v*v*M2T[k*CC + c]; }
            float inv = 1.0f / sqrtf(fmaxf(s, EPSF));
            outp[(size_t)row*CC + c] = inv;
            if (grp == 0){
                int b = row / LL, l = row - b*LL;
                g_inv_mqnT[((size_t)b*CC + c)*LL + l] = inv;
            }
        }
    } else if (grp == 6){
        int lane = tid & 31;
        float s = 0.f;
        for (int k = lane; k < KK; k += 32){ float v = qr[k]; s += v*v; }
        #pragma unroll
        for (int off = 16; off; off >>= 1) s += __shfl_xor_sync(0xffffffffu, s, off);
        if (lane == 0) g_inv_qn[row] = 1.0f / sqrtf(fmaxf(s, EPSF));
    } else {
        int lane = tid & 31;
        float s = 0.f;
        for (int k = lane; k < KK; k += 32){ float v = dr[k]; s += v*v; }
        #pragma unroll
        for (int off = 16; off; off >>= 1) s += __shfl_xor_sync(0xffffffffu, s, off);
        if (lane == 0) g_inv_dn[row] = 1.0f / sqrtf(fmaxf(s, EPSF));
    }
}

// ---------------- kernel 3: rel / wq / full / att / max-att ----------------
#define RT 25
#define RKC 40
#define DS_STR 204
#define REL_STR 208
#define WQ_STR 204
#define QS_STR 209
#define MQ_STR 204
#define OFF_DSM   0
#define OFF_REL   (OFF_DSM + RT*DS_STR)
#define OFF_WQ    (OFF_REL + RT*REL_STR)
#define OFF_QSM   (OFF_WQ  + RT*WQ_STR)
#define OFF_QSC   (OFF_QSM + RKC*QS_STR)
#define OFF_QL    (OFF_QSC + 200)
#define OFF_ISC   (OFF_QL  + 200)
#define OFF_IRS   (OFF_ISC + 32)
#define OFF_BJ    (OFF_IRS + 32)
#define RM_FLOATS (OFF_BJ + 32)
#define RM_SMEM   (RM_FLOATS*4)
#define NOUT 15

__global__ void __launch_bounds__(256) k_relmatch2(
    const float* __restrict__ q_rep, const float* __restrict__ q_last,
    const float* __restrict__ q_mask, const float* __restrict__ d_rep,
    const float* __restrict__ d_mask, float* __restrict__ out)
{
    extern __shared__ float sm[];
    float* dsm    = sm + OFF_DSM;
    float* relsm  = sm + OFF_REL;
    float* wqsm   = sm + OFF_WQ;
    float* qsm    = sm + OFF_QSM;
    float* qscale = sm + OFF_QSC;
    float* qlsm   = sm + OFF_QL;
    float* iscale = sm + OFF_ISC;
    float* irs    = sm + OFF_IRS;
    int*   bjsm   = (int*)(sm + OFF_BJ);

    int b  = blockIdx.x >> 3;
    int it = blockIdx.x & 7;
    int i0g = it * RT;
    int tid = threadIdx.x;
    const float* qb = q_rep + (size_t)b*LL*KK;
    const float* db = d_rep + (size_t)b*LL*KK + (size_t)i0g*KK;

    for (int idx = tid; idx < RT*KK; idx += 256){
        int i = idx / KK, k = idx - i*KK;
        dsm[i*DS_STR + k] = db[idx];
    }
    for (int j = tid; j < LL; j += 256)
        qscale[j] = g_inv_qn[b*LL + j] * q_mask[b*LL + j];
    for (int k = tid; k < KK; k += 256)
        qlsm[k] = q_last[(size_t)b*KK + k];
    if (tid < RT){
        int row = b*LL + i0g + tid;
        iscale[tid] = g_inv_dn[row] * d_mask[row];
    }
    __syncthreads();

    // ---- phase 1: rel GEMM ----
    int ig = tid / 40, jg = tid % 40;
    float acc[5][5];
    #pragma unroll
    for (int r = 0; r < 5; r++)
        #pragma unroll
        for (int jj = 0; jj < 5; jj++) acc[r][jj] = 0.f;

    for (int k0 = 0; k0 < KK; k0 += RKC){
        for (int idx = tid; idx < RKC*LL; idx += 256){
            int j = idx / RKC, kk = idx - j*RKC;
            qsm[kk*QS_STR + j] = qb[(size_t)j*KK + k0 + kk];
        }
        __syncthreads();
        if (tid < 200){
            #pragma unroll 4
            for (int kk = 0; kk < RKC; kk++){
                float a[5], qv[5];
                #pragma unroll
                for (int r = 0; r < 5; r++)  a[r]  = dsm[(ig*5+r)*DS_STR + k0 + kk];
                #pragma unroll
                for (int jj = 0; jj < 5; jj++) qv[jj] = qsm[kk*QS_STR + jg*5 + jj];
                #pragma unroll
                for (int r = 0; r < 5; r++)
                    #pragma unroll
                    for (int jj = 0; jj < 5; jj++) acc[r][jj] += a[r]*qv[jj];
            }
        }
        __syncthreads();
    }
    if (tid < 200){
        #pragma unroll
        for (int r = 0; r < 5; r++){
            int i = ig*5 + r; float isc = iscale[i];
            #pragma unroll
            for (int jj = 0; jj < 5; jj++){
                int j = jg*5 + jj;
                relsm[i*REL_STR + j] = acc[r][jj] * qscale[j] * isc;
            }
        }
    }
    __syncthreads();

    // ---- phase 2: per-row sum + first-occurrence argmax ----
    {
        int w = tid >> 5, lane = tid & 31;
        for (int i = w; i < RT; i += 8){
            float s = 0.f, bv = -3.402823466e38f; int bi = 0;
            for (int j = lane; j < LL; j += 32){
                float v = relsm[i*REL_STR + j];
                s += v;
                if (v > bv){ bv = v; bi = j; }
            }
            #pragma unroll
            for (int off = 16; off; off >>= 1){
                s += __shfl_xor_sync(0xffffffffu, s, off);
                float ov = __shfl_xor_sync(0xffffffffu, bv, off);
                int   oi = __shfl_xor_sync(0xffffffffu, bi, off);
                if (ov > bv || (ov == bv && oi < bi)){ bv = ov; bi = oi; }
            }
            if (lane == 0){ irs[i] = 1.0f / (s + EPSF); bjsm[i] = bi; }
        }
    }
    __syncthreads();

    // ---- phase 3: wq GEMM ----
    if (tid < 250){
        int ig2 = tid / 50, kg = tid % 50;
        float a0[5], a1[5], a2[5], a3[5];
        #pragma unroll
        for (int r = 0; r < 5; r++){ a0[r]=0.f; a1[r]=0.f; a2[r]=0.f; a3[r]=0.f; }
        const float4* qb4 = (const float4*)qb;
        for (int j = 0; j < LL; j++){
            float4 qv = qb4[j*50 + kg];
            #pragma unroll
            for (int r = 0; r < 5; r++){
                float rv = relsm[(ig2*5+r)*REL_STR + j];
                a0[r] += rv*qv.x; a1[r] += rv*qv.y;
                a2[r] += rv*qv.z; a3[r] += rv*qv.w;
            }
        }
        #pragma unroll
        for (int r = 0; r < 5; r++){
            int i = ig2*5 + r; float inv = irs[i];
            float* wp = wqsm + i*WQ_STR + kg*4;
            wp[0] = a0[r]*inv; wp[1] = a1[r]*inv; wp[2] = a2[r]*inv; wp[3] = a3[r]*inv;
        }
    }
    __syncthreads();

    // ---- phase 4: output columns, all operands staged in smem ----
    float* mqs = relsm;                    // [RT][MQ_STR]
    float* m2s = qsm;                      // [3][40][50]
    for (int idx = tid; idx < RT*KK; idx += 256){
        int i = idx / KK, k = idx - i*KK;
        mqs[i*MQ_STR + k] = qb[(size_t)bjsm[i]*KK + k];
    }
    __syncthreads();

    float accA[NOUT], accB[NOUT];
    #pragma unroll
    for (int n = 0; n < NOUT; n++){ accA[n] = 0.f; accB[n] = 0.f; }

    for (int k0 = 0; k0 < KK; k0 += 40){
        __syncthreads();
        for (int idx = tid; idx < 3*40*50; idx += 256){
            int m = idx / 2000, r = idx - m*2000;
            int kk = r / 50, c = r - kk*50;
            const float* src = (m == 0) ? g_fullM2T : (m == 1) ? g_attM2T : g_xattM2T;
            m2s[idx] = src[(size_t)(k0 + kk)*CC + c];
        }
        __syncthreads();

        int n = 0;
        for (int idx = tid; idx < RT*150; idx += 256, n++){
            int i = idx / 150, o = idx - i*150;
            int grp = o / 50, c = o - grp*50;
            const float* drow = dsm + i*DS_STR + k0;
            const float* m2p  = m2s + grp*2000 + c;
            if (grp == 0){
                const float* qlp = qlsm + k0;
                float s = accA[n];
                #pragma unroll 4
                for (int kk = 0; kk < 40; kk++)
                    s += drow[kk]*qlp[kk]*m2p[kk*50];
                accA[n] = s;
            } else if (grp == 1){
                const float* wrow = wqsm + i*WQ_STR + k0;
                float sn = accA[n], sq = accB[n];
                #pragma unroll 4
                for (int kk = 0; kk < 40; kk++){
                    float m2 = m2p[kk*50];
                    float wv = wrow[kk];
                    sn += drow[kk]*wv*m2;
                    sq += wv*wv*m2;
                }
                accA[n] = sn; accB[n] = sq;
            } else {
                const float* qrow = mqs + i*MQ_STR + k0;
                float s = accA[n];
                #pragma unroll 4
                for (int kk = 0; kk < 40; kk++)
                    s += drow[kk]*qrow[kk]*m2p[kk*50];
                accA[n] = s;
            }
        }
    }

    {
        int n = 0;
        for (int idx = tid; idx < RT*150; idx += 256, n++){
            int i = idx / 150, o = idx - i*150;
            int grp = o / 50, c = o - grp*50;
            int row = b*LL + i0g + i;
            if (grp == 0){
                out[(size_t)row*OUTC + c] = accA[n] * g_inv_fpn[(size_t)row*CC + c]
                                                     * g_inv_fqn[b*CC + c];
            } else if (grp == 1){
                out[(size_t)row*OUTC + 150 + c] =
                    accA[n] * g_inv_apn[(size_t)row*CC + c]
                            * (1.0f / sqrtf(fmaxf(accB[n], EPSF)));
            } else {
                out[(size_t)row*OUTC + 200 + c] =
                    accA[n] * g_inv_xpn[(size_t)row*CC + c]
                            * g_inv_xqn[(size_t)(b*LL + bjsm[i])*CC + c];
            }
        }
    }
}

// ---------------- kernel 4: maxpool matching — copy-A / convert-B ----------
// block = (b, c, jh); 512 threads, warps 0-12 = one m16 tile each.
// A = d (bf16 split PRECOMPUTED in g_dh/g_dl -> pure uint4 copy fills).
// B = q * M2_c, truncation-split to bf16 hi/lo at fill time (PRMT-packed).
// 3 passes: Ah*Bh + Ah*Bl + Al*Bh (fp32 accum). B frags via paired ldm_x4.
#define MSTR 72                            // bf16 per smem row (144 B)
#define SM_AH 0
#define SM_AL (208*MSTR)
#define SM_BH (2*208*MSTR)
#define SM_BL (SM_BH + 104*MSTR)
#define SM_BF16 (SM_BL + 104*MSTR)
#define MM_SMEM (SM_BF16*2 + 104*4 + 200*4)

__global__ void __launch_bounds__(512, 1) k_mp_mma(const float* __restrict__ q_rep)
{
    extern __shared__ __nv_bfloat16 smb[];
    __nv_bfloat16* Bh = smb + SM_BH;
    __nv_bfloat16* Bl = smb + SM_BL;
    float* mqs = (float*)(smb + SM_BF16);
    float* m2s = mqs + 104;
    uint32_t sbase = smem_u32(smb);
    uint4* Ah4 = (uint4*)(smb + SM_AH);    // 9 uint4 per row (144 B)
    uint4* Al4 = (uint4*)(smb + SM_AL);

    int bx = blockIdx.x;
    int jh = bx & 1;
    int c  = (bx >> 1) % CC;
    int b  = bx / (2*CC);
    int tid = threadIdx.x, wid = tid >> 5, lane = tid & 31;
    int gid = lane >> 2, tig = lane & 3;

    const float* qB = q_rep + ((size_t)b*LL + (size_t)jh*100)*KK;
    const float* m2 = g_mpM2 + (size_t)c*KK;
    const __nv_bfloat16* dhB = g_dh + (size_t)b*LL*KK;
    const __nv_bfloat16* dlB = g_dl + (size_t)b*LL*KK;

    for (int n = tid; n < 104; n += 512)
        mqs[n] = (n < 100) ? g_inv_mqnT[((size_t)b*CC + c)*LL + jh*100 + n] : 0.f;
    for (int k = tid; k < 200; k += 512) m2s[k] = m2[k];
    // zero A pad rows 200-207 once (persist across chunks; fills touch r<200)
    {
        uint4 z = {0,0,0,0};
        for (int idx = tid; idx < 144; idx += 512){
            int r = 200 + (idx >> 4) ;     // not used; simple layout below
        }
        for (int idx = tid; idx < 72; idx += 512){
            int r = 200 + idx / 9, q4 = idx % 9;
            Ah4[r*9 + q4] = z; Al4[r*9 + q4] = z;
        }
    }

    float acc[13][4];
    #pragma unroll
    for (int nt = 0; nt < 13; nt++)
        #pragma unroll
        for (int r = 0; r < 4; r++) acc[nt][r] = 0.f;

    bool mmawarp = (wid < 13);
    uint32_t a_off = (uint32_t)((wid*16 + (lane & 15))*MSTR*2 + ((lane >> 4)*16));
    // B x4 pair addressing: rows (nt2*16 + ((lane>>4)&1)*8 + (lane&7)), colbyte ((lane>>3)&1)*16
    uint32_t b_off4 = (uint32_t)((((lane >> 4) & 1)*8 + (lane & 7))*MSTR*2
                                 + (((lane >> 3) & 1)*16));
    uint32_t b_off2 = (uint32_t)((lane & 7)*MSTR*2 + (((lane >> 3) & 1)*16));

    #pragma unroll
    for (int kc = 0; kc < 4; kc++){
        const int k0 = kc*64;
        __syncthreads();
        // ---- A fill: pure uint4 copies from precomputed d split ----
        if (kc < 3){
            for (int idx = tid; idx < 1600; idx += 512){
                int r = idx >> 3, q4 = idx & 7;
                const __nv_bfloat16* sh = dhB + (size_t)r*KK + k0 + q4*8;
                const __nv_bfloat16* sl = dlB + (size_t)r*KK + k0 + q4*8;
                Ah4[r*9 + q4] = *(const uint4*)sh;
                Al4[r*9 + q4] = *(const uint4*)sl;
            }
        } else {
            uint4 z = {0,0,0,0};
            for (int idx = tid; idx < 400; idx += 512){
                int r = idx >> 1, q4 = idx & 1;
                if (q4 == 0){
                    Ah4[r*9] = *(const uint4*)(dhB + (size_t)r*KK + 192);
                    Al4[r*9] = *(const uint4*)(dlB + (size_t)r*KK + 192);
                } else {
                    Ah4[r*9 + 1] = z; Al4[r*9 + 1] = z;
                }
            }
        }
        // ---- B fill: convert q * M2 with truncation split, pair-packed ----
        if (kc < 3){
            for (int idx = tid; idx < 3328; idx += 512){
                int n = idx >> 5, kk2 = (idx & 31) << 1, gk = k0 + kk2;
                uint32_t hp = 0u, lp = 0u;
                if (n < 100){
                    float2 qv = *(const float2*)(qB + (size_t)n*KK + gk);
                    float v0 = qv.x * m2s[gk], v1 = qv.y * m2s[gk+1];
                    uint32_t u0 = __float_as_uint(v0), u1 = __float_as_uint(v1);
                    float l0 = v0 - __uint_as_float(u0 & 0xffff0000u);
                    float l1 = v1 - __uint_as_float(u1 & 0xffff0000u);
                    hp = __byte_perm(u0, u1, 0x7632);
                    lp = __byte_perm(__float_as_uint(l0), __float_as_uint(l1), 0x7632);
                }
                *(uint32_t*)((char*)Bh + n*144 + kk2*2) = hp;
                *(uint32_t*)((char*)Bl + n*144 + kk2*2) = lp;
            }
        } else {
            for (int idx = tid; idx < 832; idx += 512){
                int n = idx >> 3, kk2 = (idx & 7) << 1, gk = 192 + kk2;
                uint32_t hp = 0u, lp = 0u;
                if (n < 100 && gk < 200){
                    float2 qv = *(const float2*)(qB + (size_t)n*KK + gk);
                    float v0 = qv.x * m2s[gk], v1 = qv.y * m2s[gk+1];
                    uint32_t u0 = __float_as_uint(v0), u1 = __float_as_uint(v1);
                    float l0 = v0 - __uint_as_float(u0 & 0xffff0000u);
                    float l1 = v1 - __uint_as_float(u1 & 0xffff0000u);
                    hp = __byte_perm(u0, u1, 0x7632);
                    lp = __byte_perm(__float_as_uint(l0), __float_as_uint(l1), 0x7632);
                }
                *(uint32_t*)((char*)Bh + n*144 + kk2*2) = hp;
                *(uint32_t*)((char*)Bl + n*144 + kk2*2) = lp;
            }
        }
        __syncthreads();

        if (mmawarp){
            const int nks = (kc == 3) ? 1 : 4;
            for (int ks = 0; ks < nks; ks++){
                uint32_t kbb = (uint32_t)(ks*32);
                uint32_t ah[4], al[4];
                ldm_x4(ah, sbase + (uint32_t)(SM_AH*2) + a_off + kbb);
                ldm_x4(al, sbase + (uint32_t)(SM_AL*2) + a_off + kbb);
                #pragma unroll
                for (int nt2 = 0; nt2 < 6; nt2++){
                    uint32_t bo = (uint32_t)(nt2*16*MSTR*2) + b_off4 + kbb;
                    uint32_t bh4[4], bl4[4];
                    ldm_x4(bh4, sbase + (uint32_t)(SM_BH*2) + bo);
                    ldm_x4(bl4, sbase + (uint32_t)(SM_BL*2) + bo);
                    mma16816(acc[2*nt2  ], ah, bh4[0], bh4[1]);
                    mma16816(acc[2*nt2  ], ah, bl4[0], bl4[1]);
                    mma16816(acc[2*nt2  ], al, bh4[0], bh4[1]);
                    mma16816(acc[2*nt2+1], ah, bh4[2], bh4[3]);
                    mma16816(acc[2*nt2+1], ah, bl4[2], bl4[3]);
                    mma16816(acc[2*nt2+1], al, bh4[2], bh4[3]);
                }
                {   // last n-tile (12)
                    uint32_t bo = (uint32_t)(12*8*MSTR*2) + b_off2 + kbb;
                    uint32_t bh2[2], bl2[2];
                    ldm_x2(bh2, sbase + (uint32_t)(SM_BH*2) + bo);
                    ldm_x2(bl2, sbase + (uint32_t)(SM_BL*2) + bo);
                    mma16816(acc[12], ah, bh2[0], bh2[1]);
                    mma16816(acc[12], ah, bl2[0], bl2[1]);
                    mma16816(acc[12], al, bh2[0], bh2[1]);
                }
            }
        }
    }

    // ---- epilogue: scale by inv_mqn[j], reduce max/sum over this j-half ----
    if (mmawarp){
        #pragma unroll
        for (int hh = 0; hh < 2; hh++){
            float mx = -3.402823466e38f, sum = 0.f;
            #pragma unroll
            for (int nt = 0; nt < 13; nt++){
                int n0 = nt*8 + 2*tig;
                float v0 = acc[nt][hh*2 + 0] * mqs[n0];
                float v1 = acc[nt][hh*2 + 1] * mqs[n0 + 1];
                if (n0     < 100){ mx = fmaxf(mx, v0); sum += v0; }
                if (n0 + 1 < 100){ mx = fmaxf(mx, v1); sum += v1; }
            }
            mx = fmaxf(mx, __shfl_xor_sync(0xffffffffu, mx, 1));
            mx = fmaxf(mx, __shfl_xor_sync(0xffffffffu, mx, 2));
            sum += __shfl_xor_sync(0xffffffffu, sum, 1);
            sum += __shfl_xor_sync(0xffffffffu, sum, 2);
            if (tig == 0){
                int i = wid*16 + gid + hh*8;
                if (i < 200){
                    size_t m = (size_t)b*10240 + (size_t)c*LL + i;
                    g_pmax[jh][m] = mx;
                    g_psum[jh][m] = sum;
                }
            }
        }
    }
}

// ---------------- kernel 5: combine j-halves, apply inv_mpn ----------------
__global__ void k_mpfin(float* __restrict__ out)
{
    int idx = blockIdx.x*256 + threadIdx.x;
    if (idx >= BB*LL*CC) return;
    int b = idx / (LL*CC), m = idx - b*(LL*CC);
    int c = m / LL, i = m - c*LL;
    size_t pi = (size_t)b*10240 + m;
    float invp = g_inv_mpn[((size_t)b*LL + i)*CC + c];
    float mx = fmaxf(g_pmax[0][pi], g_pmax[1][pi]) * invp;
    float sm = (g_psum[0][pi] + g_psum[1][pi]) * invp;
    float* o = out + ((size_t)b*LL + i)*OUTC;
    o[ 50 + c] = mx;
    o[100 + c] = sm * (1.0f/200.0f);
}

// ---------------- launcher -------------------------------------------------
extern "C" void kernel_launch(void* const* d_in, const int* in_sizes, int n_in,
                              void* d_out, int out_size)
{
    const float* q_rep  = (const float*)d_in[0];
    const float* q_last = (const float*)d_in[1];
    const float* q_mask = (const float*)d_in[2];
    const float* d_rep  = (const float*)d_in[3];
    // d_in[4] = d_last (unused by reference)
    const float* d_mask = (const float*)d_in[5];
    const float* fullM  = (const float*)d_in[6];
    const float* mpM    = (const float*)d_in[7];
    const float* attM   = (const float*)d_in[8];
    const float* xattM  = (const float*)d_in[9];
    float* out = (float*)d_out;

    k_setup<<<1322, 256>>>(fullM, mpM, attM, xattM, d_rep, q_last);
    k_norms<<<BB*LL, 512>>>(q_rep, d_rep);

    cudaFuncSetAttribute(k_relmatch2, cudaFuncAttributeMaxDynamicSharedMemorySize, RM_SMEM);
    k_relmatch2<<<BB*8, 256, RM_SMEM>>>(q_rep, q_last, q_mask, d_rep, d_mask, out);

    cudaFuncSetAttribute(k_mp_mma, cudaFuncAttributeMaxDynamicSharedMemorySize, MM_SMEM);
    k_mp_mma<<<BB*CC*2, 512, MM_SMEM>>>(q_rep);

    k_mpfin<<<(BB*LL*CC + 255)/256, 256>>>(out);
}